// round 1
// baseline (speedup 1.0000x reference)
#include <cuda_runtime.h>
#include <cstddef>

// ---------------------------------------------------------------------------
// SAGE_37563783971092: 3-layer GraphSAGE (mean aggregator), fp32.
//   layer(h, E): h_dst = relu( h[:n_dst] @ Ws + (segmean(h[e_src], e_dst)) @ Wn + b )
// Pipeline per layer: zero agg/deg -> edge scatter (atomicAdd) -> divide by deg
//                     -> fused dual GEMM (+bias, +relu) .
// ---------------------------------------------------------------------------

namespace {
constexpr int kN1 = 262144, kN2 = 32768, kN3 = 8192;
constexpr int kE0 = 1310720, kE1 = 327680, kE2 = 81920;
constexpr int kF = 100, kH = 256, kC = 47;
}  // namespace

// Scratch (device globals; no allocations allowed).
__device__ float g_agg0[(size_t)kN1 * kF];   // 105 MB
__device__ float g_deg0[kN1];
__device__ float g_h1[(size_t)kN1 * kH];     // 268 MB
__device__ float g_agg1[(size_t)kN2 * kH];   // 33.5 MB
__device__ float g_deg1[kN2];
__device__ float g_h2[(size_t)kN2 * kH];     // 33.5 MB
__device__ float g_agg2[(size_t)kN3 * kH];   // 8.4 MB
__device__ float g_deg2[kN3];

// ---------------------------------------------------------------------------
__global__ void zero_kern(float4* __restrict__ p, int n4) {
    int i = blockIdx.x * blockDim.x + threadIdx.x;
    int stride = gridDim.x * blockDim.x;
    float4 z = make_float4(0.f, 0.f, 0.f, 0.f);
    for (; i < n4; i += stride) p[i] = z;
}

// One warp per edge. K floats per row, K % 4 == 0, rows are 16B aligned.
template <int K>
__global__ void scatter_kern(const float* __restrict__ feat,
                             const int* __restrict__ esrc,
                             const int* __restrict__ edst, int nE,
                             float* __restrict__ agg, float* __restrict__ deg) {
    int warp = (blockIdx.x * blockDim.x + threadIdx.x) >> 5;
    int lane = threadIdx.x & 31;
    if (warp >= nE) return;
    int s = __ldg(esrc + warp);
    int d = __ldg(edst + warp);
    const float4* src = reinterpret_cast<const float4*>(feat + (size_t)s * K);
    float* dst = agg + (size_t)d * K;
    constexpr int NV = K / 4;  // 25 (K=100) or 64 (K=256)
#pragma unroll
    for (int v = lane; v < NV; v += 32) {
        float4 f = __ldg(src + v);
        atomicAdd(dst + 4 * v + 0, f.x);
        atomicAdd(dst + 4 * v + 1, f.y);
        atomicAdd(dst + 4 * v + 2, f.z);
        atomicAdd(dst + 4 * v + 3, f.w);
    }
    if (lane == 31) atomicAdd(deg + d, 1.0f);
}

// In-place: agg[row][*] *= 1/max(deg[row],1)
template <int K>
__global__ void divide_kern(float* __restrict__ agg, const float* __restrict__ deg,
                            int nrows) {
    constexpr int KV = K / 4;
    int i = blockIdx.x * blockDim.x + threadIdx.x;
    if (i >= nrows * KV) return;
    int row = i / KV;
    float r = 1.0f / fmaxf(__ldg(deg + row), 1.0f);
    float4* p = reinterpret_cast<float4*>(agg) + i;
    float4 v = *p;
    v.x *= r; v.y *= r; v.z *= r; v.w *= r;
    *p = v;
}

// ---------------------------------------------------------------------------
// Fused dual GEMM: out = act( Aself @ Ws + Aneigh @ Wn + b ), tiles 128x128xBK8.
// M (gridDim.x*128) is a multiple of 128 for all layers. Aneigh has ld = K1.
// Weights are [K1, NCOLS] row-major. 256 threads, 8x8 outputs per thread with
// 16-strided fragment mapping (conflict-free LDS).
// ---------------------------------------------------------------------------
template <int K1, int NCOLS, bool RELU>
__global__ void __launch_bounds__(256, 2)
sage_gemm(const float* __restrict__ Aself, int ldA0,
          const float* __restrict__ Aneigh,
          const float* __restrict__ Ws, const float* __restrict__ Wn,
          const float* __restrict__ bias, float* __restrict__ out, int ldout) {
    constexpr int BM = 128, BN = 128, BK = 8;
    __shared__ float As[BK][BM];
    __shared__ float Bs[BK][BN];

    const int tid = threadIdx.x;
    const int tx = tid & 15;        // column group
    const int ty = tid >> 4;        // row group
    const int mBlock = blockIdx.x * BM;
    const int nBlock = blockIdx.y * BN;

    float acc[8][8];
#pragma unroll
    for (int i = 0; i < 8; i++)
#pragma unroll
        for (int j = 0; j < 8; j++) acc[i][j] = 0.f;

    // A tile loaders: 2 threads per row, one float4 each (rows are 16B aligned
    // because ldA ∈ {100, 256}, both %4==0).
    const int am = tid >> 1;
    const int ak = (tid & 1) * 4;
    // B tile loaders: one float4 per thread (8 k-rows x 32 float4s).
    const int bk = tid >> 5;
    const int bn = (tid & 31) * 4;

#pragma unroll
    for (int phase = 0; phase < 2; ++phase) {
        const float* A = phase ? Aneigh : Aself;
        const int ldA = phase ? K1 : ldA0;
        const float* W = phase ? Wn : Ws;
        constexpr int NK = (K1 + BK - 1) / BK;
        for (int kc = 0; kc < NK; ++kc) {
            const int k0 = kc * BK;
            __syncthreads();
            // ---- load A[128][8] -> As[k][m]
            {
                const int gm = mBlock + am;
                const int gk = k0 + ak;
                const float* ap = A + (size_t)gm * ldA + gk;
                float4 v;
                if (gk + 3 < K1) {
                    v = *reinterpret_cast<const float4*>(ap);
                } else {
                    v.x = (gk + 0 < K1) ? ap[0] : 0.f;
                    v.y = (gk + 1 < K1) ? ap[1] : 0.f;
                    v.z = (gk + 2 < K1) ? ap[2] : 0.f;
                    v.w = (gk + 3 < K1) ? ap[3] : 0.f;
                }
                As[ak + 0][am] = v.x;
                As[ak + 1][am] = v.y;
                As[ak + 2][am] = v.z;
                As[ak + 3][am] = v.w;
            }
            // ---- load W[8][128] -> Bs[k][n]
            {
                const int gk = k0 + bk;
                const int gn = nBlock + bn;
                float4 v = make_float4(0.f, 0.f, 0.f, 0.f);
                if (gk < K1) {
                    if constexpr (NCOLS % 4 == 0) {
                        v = *reinterpret_cast<const float4*>(W + (size_t)gk * NCOLS + gn);
                    } else {
                        const float* wp = W + (size_t)gk * NCOLS;
                        if (gn + 0 < NCOLS) v.x = wp[gn + 0];
                        if (gn + 1 < NCOLS) v.y = wp[gn + 1];
                        if (gn + 2 < NCOLS) v.z = wp[gn + 2];
                        if (gn + 3 < NCOLS) v.w = wp[gn + 3];
                    }
                }
                Bs[bk][bn + 0] = v.x;
                Bs[bk][bn + 1] = v.y;
                Bs[bk][bn + 2] = v.z;
                Bs[bk][bn + 3] = v.w;
            }
            __syncthreads();
            // ---- FMA
#pragma unroll
            for (int kk = 0; kk < BK; ++kk) {
                float a[8], b[8];
#pragma unroll
                for (int i = 0; i < 8; i++) a[i] = As[kk][ty + 16 * i];
#pragma unroll
                for (int j = 0; j < 8; j++) b[j] = Bs[kk][tx + 16 * j];
#pragma unroll
                for (int i = 0; i < 8; i++)
#pragma unroll
                    for (int j = 0; j < 8; j++) acc[i][j] += a[i] * b[j];
            }
        }
    }

    // ---- epilogue: + bias, optional relu
#pragma unroll
    for (int j = 0; j < 8; j++) {
        const int gn = nBlock + tx + 16 * j;
        if (gn >= NCOLS) continue;
        const float bv = __ldg(bias + gn);
#pragma unroll
        for (int i = 0; i < 8; i++) {
            const int gm = mBlock + ty + 16 * i;
            float v = acc[i][j] + bv;
            if (RELU) v = fmaxf(v, 0.f);
            out[(size_t)gm * ldout + gn] = v;
        }
    }
}

// ---------------------------------------------------------------------------
static inline int cdiv_host(long long a, long long b) { return (int)((a + b - 1) / b); }

extern "C" void kernel_launch(void* const* d_in, const int* in_sizes, int n_in,
                              void* d_out, int out_size) {
    (void)in_sizes; (void)n_in; (void)out_size;
    const float* x   = (const float*)d_in[0];
    const int* es0   = (const int*)d_in[1];
    const int* ed0   = (const int*)d_in[2];
    const int* es1   = (const int*)d_in[3];
    const int* ed1   = (const int*)d_in[4];
    const int* es2   = (const int*)d_in[5];
    const int* ed2   = (const int*)d_in[6];
    const float* Ws0 = (const float*)d_in[7];
    const float* Wn0 = (const float*)d_in[8];
    const float* b0  = (const float*)d_in[9];
    const float* Ws1 = (const float*)d_in[10];
    const float* Wn1 = (const float*)d_in[11];
    const float* b1  = (const float*)d_in[12];
    const float* Ws2 = (const float*)d_in[13];
    const float* Wn2 = (const float*)d_in[14];
    const float* b2  = (const float*)d_in[15];
    float* out = (float*)d_out;

    float *agg0, *deg0, *h1, *agg1, *deg1, *h2, *agg2, *deg2;
    cudaGetSymbolAddress((void**)&agg0, g_agg0);
    cudaGetSymbolAddress((void**)&deg0, g_deg0);
    cudaGetSymbolAddress((void**)&h1,   g_h1);
    cudaGetSymbolAddress((void**)&agg1, g_agg1);
    cudaGetSymbolAddress((void**)&deg1, g_deg1);
    cudaGetSymbolAddress((void**)&h2,   g_h2);
    cudaGetSymbolAddress((void**)&agg2, g_agg2);
    cudaGetSymbolAddress((void**)&deg2, g_deg2);

    const int T = 256;

    // ---------------- layer 0: x[1M,100] -> h1[262144,256]
    {
        int n4a = kN1 * kF / 4, n4d = kN1 / 4;
        zero_kern<<<cdiv_host(n4a, T), T>>>((float4*)agg0, n4a);
        zero_kern<<<cdiv_host(n4d, T), T>>>((float4*)deg0, n4d);
        scatter_kern<kF><<<cdiv_host((long long)kE0 * 32, T), T>>>(x, es0, ed0, kE0, agg0, deg0);
        divide_kern<kF><<<cdiv_host((long long)kN1 * (kF / 4), T), T>>>(agg0, deg0, kN1);
        sage_gemm<kF, kH, true><<<dim3(kN1 / 128, kH / 128), T>>>(
            x, kF, agg0, Ws0, Wn0, b0, h1, kH);
    }
    // ---------------- layer 1: h1 -> h2[32768,256]
    {
        int n4a = kN2 * kH / 4, n4d = kN2 / 4;
        zero_kern<<<cdiv_host(n4a, T), T>>>((float4*)agg1, n4a);
        zero_kern<<<cdiv_host(n4d, T), T>>>((float4*)deg1, n4d);
        scatter_kern<kH><<<cdiv_host((long long)kE1 * 32, T), T>>>(h1, es1, ed1, kE1, agg1, deg1);
        divide_kern<kH><<<cdiv_host((long long)kN2 * (kH / 4), T), T>>>(agg1, deg1, kN2);
        sage_gemm<kH, kH, true><<<dim3(kN2 / 128, kH / 128), T>>>(
            h1, kH, agg1, Ws1, Wn1, b1, h2, kH);
    }
    // ---------------- layer 2: h2 -> out[8192,47]
    {
        int n4a = kN3 * kH / 4, n4d = kN3 / 4;
        zero_kern<<<cdiv_host(n4a, T), T>>>((float4*)agg2, n4a);
        zero_kern<<<cdiv_host(n4d, T), T>>>((float4*)deg2, n4d);
        scatter_kern<kH><<<cdiv_host((long long)kE2 * 32, T), T>>>(h2, es2, ed2, kE2, agg2, deg2);
        divide_kern<kH><<<cdiv_host((long long)kN3 * (kH / 4), T), T>>>(agg2, deg2, kN3);
        sage_gemm<kH, kC, false><<<dim3(kN3 / 128, 1), T>>>(
            h2, kH, agg2, Ws2, Wn2, b2, out, kC);
    }
}

// round 3
// speedup vs baseline: 1.4763x; 1.4763x over previous
#include <cuda_runtime.h>
#include <cuda_bf16.h>
#include <cstdint>
#include <cstddef>

// ---------------------------------------------------------------------------
// SAGE 3-layer GraphSAGE. Per layer:
//   zero agg/deg -> edge scatter (atomicAdd) -> split agg to bf16 hi/lo with
//   fused 1/deg scaling -> mma.sync bf16x3 dual GEMM (fp32-accurate) with
//   bias+relu epilogue that also emits the bf16 hi/lo split of the activation
//   needed by the next layer's "self" operand.
// No tcgen05 (ptxas targets sm_103 without the 'a' feature set here).
// ---------------------------------------------------------------------------

namespace {
constexpr int kN1 = 262144, kN2 = 32768, kN3 = 8192;
constexpr int kE0 = 1310720, kE1 = 327680, kE2 = 81920;
constexpr int kF = 100, kH = 256, kC = 47;
}  // namespace

// -------- fp32 scratch ------------------------------------------------------
__device__ float g_agg0[(size_t)kN1 * kF];
__device__ float g_deg0[kN1];
__device__ float g_h1[(size_t)kN1 * kH];
__device__ float g_agg1[(size_t)kN2 * kH];
__device__ float g_deg1[kN2];
__device__ float g_h2[(size_t)kN2 * kH];
__device__ float g_agg2[(size_t)kN3 * kH];
__device__ float g_deg2[kN3];

// -------- bf16 split operand buffers (K padded to 128/256) ------------------
__device__ __nv_bfloat16 g_xs_hi[(size_t)kN1 * 128], g_xs_lo[(size_t)kN1 * 128];
__device__ __nv_bfloat16 g_a0_hi[(size_t)kN1 * 128], g_a0_lo[(size_t)kN1 * 128];
__device__ __nv_bfloat16 g_h1s_hi[(size_t)kN2 * 256], g_h1s_lo[(size_t)kN2 * 256];
__device__ __nv_bfloat16 g_a1_hi[(size_t)kN2 * 256], g_a1_lo[(size_t)kN2 * 256];
__device__ __nv_bfloat16 g_h2s_hi[(size_t)kN3 * 256], g_h2s_lo[(size_t)kN3 * 256];
__device__ __nv_bfloat16 g_a2_hi[(size_t)kN3 * 256], g_a2_lo[(size_t)kN3 * 256];

// -------- pre-split weights: [2 phases][KPAD][NPAD] -------------------------
__device__ __nv_bfloat16 g_w0_hi[2 * 128 * 256], g_w0_lo[2 * 128 * 256];
__device__ __nv_bfloat16 g_w1_hi[2 * 256 * 256], g_w1_lo[2 * 256 * 256];
__device__ __nv_bfloat16 g_w2_hi[2 * 256 * 128], g_w2_lo[2 * 256 * 128];

// ======================== PTX helpers (arch-agnostic) ========================
__device__ __forceinline__ uint32_t smem_u32(const void* p) {
    return (uint32_t)__cvta_generic_to_shared(p);
}
__device__ __forceinline__ void ldsm4(uint32_t* r, uint32_t addr) {
    asm volatile("ldmatrix.sync.aligned.m8n8.x4.shared.b16 {%0,%1,%2,%3}, [%4];"
                 : "=r"(r[0]), "=r"(r[1]), "=r"(r[2]), "=r"(r[3]) : "r"(addr));
}
__device__ __forceinline__ void ldsm4t(uint32_t* r, uint32_t addr) {
    asm volatile("ldmatrix.sync.aligned.m8n8.x4.trans.shared.b16 {%0,%1,%2,%3}, [%4];"
                 : "=r"(r[0]), "=r"(r[1]), "=r"(r[2]), "=r"(r[3]) : "r"(addr));
}
__device__ __forceinline__ void mma_bf16(float* d, const uint32_t* a,
                                         uint32_t b0, uint32_t b1) {
    asm volatile(
        "mma.sync.aligned.m16n8k16.row.col.f32.bf16.bf16.f32 "
        "{%0,%1,%2,%3}, {%4,%5,%6,%7}, {%8,%9}, {%0,%1,%2,%3};"
        : "+f"(d[0]), "+f"(d[1]), "+f"(d[2]), "+f"(d[3])
        : "r"(a[0]), "r"(a[1]), "r"(a[2]), "r"(a[3]), "r"(b0), "r"(b1));
}
// pack two fp32 into one bf16x2 register (lo = a, hi = b)
__device__ __forceinline__ uint32_t cvt_bf16x2(float a, float b) {
    uint32_t r;
    asm("cvt.rn.bf16x2.f32 %0, %1, %2;" : "=r"(r) : "f"(b), "f"(a));
    return r;
}

// ======================== small kernels =====================================
__global__ void zero_kern(float4* __restrict__ p, int n4) {
    int i = blockIdx.x * blockDim.x + threadIdx.x;
    int stride = gridDim.x * blockDim.x;
    float4 z = make_float4(0.f, 0.f, 0.f, 0.f);
    for (; i < n4; i += stride) p[i] = z;
}

// One warp per edge; scalar atomicAdd (proven path; ptxas lowers to RED).
template <int K>
__global__ void scatter_kern(const float* __restrict__ feat,
                             const int* __restrict__ esrc,
                             const int* __restrict__ edst, int nE,
                             float* __restrict__ agg, float* __restrict__ deg) {
    int warp = (blockIdx.x * blockDim.x + threadIdx.x) >> 5;
    int lane = threadIdx.x & 31;
    if (warp >= nE) return;
    int s = __ldg(esrc + warp);
    int d = __ldg(edst + warp);
    const float4* src = reinterpret_cast<const float4*>(feat + (size_t)s * K);
    float* dst = agg + (size_t)d * K;
    constexpr int NV = K / 4;
#pragma unroll
    for (int v = lane; v < NV; v += 32) {
        float4 f = __ldg(src + v);
        atomicAdd(dst + 4 * v + 0, f.x);
        atomicAdd(dst + 4 * v + 1, f.y);
        atomicAdd(dst + 4 * v + 2, f.z);
        atomicAdd(dst + 4 * v + 3, f.w);
    }
    if (lane == 31) atomicAdd(deg + d, 1.0f);
}

// Split fp32 -> bf16 hi (bit-truncation) + lo (RN of remainder), K -> KPAD
// zero-padded, optional 1/max(deg,1) scaling. 4 elements per thread.
template <int K, int KPAD, bool SCALE>
__global__ void split_kern(const float* __restrict__ in,
                           const float* __restrict__ deg, int rows,
                           uint2* __restrict__ hi, uint2* __restrict__ lo) {
    constexpr int PR = KPAD / 4;
    int idx = blockIdx.x * blockDim.x + threadIdx.x;
    if (idx >= rows * PR) return;
    int row = idx / PR, kq = idx % PR;
    int k4 = kq * 4;
    float4 v = make_float4(0.f, 0.f, 0.f, 0.f);
    if (k4 < K)  // K % 4 == 0, so full vector or fully out of range
        v = *reinterpret_cast<const float4*>(in + (size_t)row * K + k4);
    if (SCALE) {
        float r = 1.f / fmaxf(__ldg(deg + row), 1.f);
        v.x *= r; v.y *= r; v.z *= r; v.w *= r;
    }
    uint32_t hx = __float_as_uint(v.x) & 0xFFFF0000u;
    uint32_t hy = __float_as_uint(v.y) & 0xFFFF0000u;
    uint32_t hz = __float_as_uint(v.z) & 0xFFFF0000u;
    uint32_t hw = __float_as_uint(v.w) & 0xFFFF0000u;
    float lx = v.x - __uint_as_float(hx);
    float ly = v.y - __uint_as_float(hy);
    float lz = v.z - __uint_as_float(hz);
    float lw = v.w - __uint_as_float(hw);
    uint2 ho, lv;
    ho.x = (hx >> 16) | hy;
    ho.y = (hz >> 16) | hw;
    lv.x = cvt_bf16x2(lx, ly);
    lv.y = cvt_bf16x2(lz, lw);
    size_t o = (size_t)row * PR + kq;
    hi[o] = ho;
    lo[o] = lv;
}

// Pre-split weights into [2][KPAD][NPAD] bf16 hi/lo with zero padding.
template <int K1, int NCOLS, int KPAD, int NPAD>
__global__ void prep_w(const float* __restrict__ Ws, const float* __restrict__ Wn,
                       __nv_bfloat16* __restrict__ hi, __nv_bfloat16* __restrict__ lo) {
    int idx = blockIdx.x * blockDim.x + threadIdx.x;
    constexpr int TOT = 2 * KPAD * NPAD;
    if (idx >= TOT) return;
    int phase = idx / (KPAD * NPAD);
    int rem = idx % (KPAD * NPAD);
    int k = rem / NPAD, n = rem % NPAD;
    float v = 0.f;
    if (k < K1 && n < NCOLS) v = (phase ? Wn : Ws)[(size_t)k * NCOLS + n];
    uint32_t h = __float_as_uint(v) & 0xFFFF0000u;
    float l = v - __uint_as_float(h);
    hi[idx] = __ushort_as_bfloat16((unsigned short)(h >> 16));
    lo[idx] = __float2bfloat16(l);
}

// ======================== mma.sync bf16x3 dual GEMM =========================
// out[M, NCOLS] = act( self @ Ws + neigh @ Wn + bias ); operands pre-split
// bf16 hi/lo with zero-padded K (KPAD). Block tile 128x128xBK64, 8 warps of
// 64x32. Optionally writes the bf16 hi/lo split of the activation for rows
// < split_rows (next layer's self operand).
template <int KPAD, int NCOLS, int NPAD, bool RELU, bool WSPLIT>
__global__ void __launch_bounds__(256, 2)
gemm_mma(const __nv_bfloat16* __restrict__ As_hi, const __nv_bfloat16* __restrict__ As_lo,
         const __nv_bfloat16* __restrict__ An_hi, const __nv_bfloat16* __restrict__ An_lo,
         const __nv_bfloat16* __restrict__ W_hi, const __nv_bfloat16* __restrict__ W_lo,
         const float* __restrict__ bias, float* __restrict__ out,
         uint32_t* __restrict__ sp_hi, uint32_t* __restrict__ sp_lo, int split_rows) {
    constexpr int BK = 64;
    constexpr int AST = 72;                 // A smem row stride (bf16 units)
    constexpr int BST = 136;                // B smem row stride
    constexpr int ABYTES = 128 * AST * 2;   // 18432
    constexpr int BBYTES = BK * BST * 2;    // 17408
    constexpr int CPP = KPAD / BK;          // chunks per phase

    extern __shared__ char smem[];
    __nv_bfloat16* sAhi = (__nv_bfloat16*)(smem);
    __nv_bfloat16* sAlo = (__nv_bfloat16*)(smem + ABYTES);
    __nv_bfloat16* sBhi = (__nv_bfloat16*)(smem + 2 * ABYTES);
    __nv_bfloat16* sBlo = (__nv_bfloat16*)(smem + 2 * ABYTES + BBYTES);
    const uint32_t su = smem_u32(smem);

    const int tid = threadIdx.x;
    const int lane = tid & 31, wid = tid >> 5;
    const int wm = wid & 1, wn = wid >> 1;   // warp grid 2(m) x 4(n)
    const int mBlock = blockIdx.x * 128, nBlock = blockIdx.y * 128;

    float acc[4][4][4];
#pragma unroll
    for (int i = 0; i < 4; i++)
#pragma unroll
        for (int j = 0; j < 4; j++)
#pragma unroll
            for (int r = 0; r < 4; r++) acc[i][j][r] = 0.f;

    // ldmatrix lane geometry (canonical x4 mapping)
    const int lr = lane & 15;
    const int lc = (lane >> 4) * 8;
    const uint32_t aHiBase = su + 2u * (uint32_t)((wm * 64 + lr) * AST + lc);
    const uint32_t bHiBase = su + 2u * (uint32_t)ABYTES +
                             2u * (uint32_t)(lr * BST + wn * 32 + lc);

    for (int c = 0; c < 2 * CPP; ++c) {
        const int phase = c / CPP;
        const int k0 = (c % CPP) * BK;
        const __nv_bfloat16* Ahi = phase ? An_hi : As_hi;
        const __nv_bfloat16* Alo = phase ? An_lo : As_lo;
        if (c) __syncthreads();
        // ---- A tiles: 128 rows x 64 bf16, hi+lo (uint4 = 8 bf16)
#pragma unroll
        for (int it = 0; it < 4; ++it) {
            int u = tid + it * 256;
            int r = u >> 3, c8 = u & 7;
            size_t g = (size_t)(mBlock + r) * KPAD + k0 + c8 * 8;
            *reinterpret_cast<uint4*>(sAhi + r * AST + c8 * 8) =
                *reinterpret_cast<const uint4*>(Ahi + g);
            *reinterpret_cast<uint4*>(sAlo + r * AST + c8 * 8) =
                *reinterpret_cast<const uint4*>(Alo + g);
        }
        // ---- B tiles: 64 rows(k) x 128 bf16(n), hi+lo
#pragma unroll
        for (int it = 0; it < 4; ++it) {
            int u = tid + it * 256;
            int r = u >> 4, c8 = u & 15;
            size_t g = (size_t)phase * KPAD * NPAD + (size_t)(k0 + r) * NPAD +
                       nBlock + c8 * 8;
            *reinterpret_cast<uint4*>(sBhi + r * BST + c8 * 8) =
                *reinterpret_cast<const uint4*>(W_hi + g);
            *reinterpret_cast<uint4*>(sBlo + r * BST + c8 * 8) =
                *reinterpret_cast<const uint4*>(W_lo + g);
        }
        __syncthreads();
#pragma unroll
        for (int k16 = 0; k16 < BK / 16; ++k16) {
            const uint32_t kk = k16 * 16;
            uint32_t ah[4][4], bh[2][4];
            // B-hi (two n-tile pairs) and A-hi (4 m-tiles)
#pragma unroll
            for (int p = 0; p < 2; ++p)
                ldsm4t(bh[p], bHiBase + 2u * (kk * BST + p * 16));
#pragma unroll
            for (int mt = 0; mt < 4; ++mt)
                ldsm4(ah[mt], aHiBase + 2u * (mt * 16 * AST + kk));
            // hi*hi
#pragma unroll
            for (int mt = 0; mt < 4; ++mt)
#pragma unroll
                for (int nt = 0; nt < 4; ++nt)
                    mma_bf16(acc[mt][nt], ah[mt], bh[nt >> 1][(nt & 1) * 2],
                             bh[nt >> 1][(nt & 1) * 2 + 1]);
            {   // hi*lo  (B-lo; then ah dead)
                uint32_t bl[2][4];
#pragma unroll
                for (int p = 0; p < 2; ++p)
                    ldsm4t(bl[p], bHiBase + (uint32_t)BBYTES + 2u * (kk * BST + p * 16));
#pragma unroll
                for (int mt = 0; mt < 4; ++mt)
#pragma unroll
                    for (int nt = 0; nt < 4; ++nt)
                        mma_bf16(acc[mt][nt], ah[mt], bl[nt >> 1][(nt & 1) * 2],
                                 bl[nt >> 1][(nt & 1) * 2 + 1]);
            }
            {   // lo*hi  (A-lo)
                uint32_t al[4][4];
#pragma unroll
                for (int mt = 0; mt < 4; ++mt)
                    ldsm4(al[mt], aHiBase + (uint32_t)ABYTES + 2u * (mt * 16 * AST + kk));
#pragma unroll
                for (int mt = 0; mt < 4; ++mt)
#pragma unroll
                    for (int nt = 0; nt < 4; ++nt)
                        mma_bf16(acc[mt][nt], al[mt], bh[nt >> 1][(nt & 1) * 2],
                                 bh[nt >> 1][(nt & 1) * 2 + 1]);
            }
        }
    }

    // ---- epilogue: bias (+relu), store fp32, optional bf16 split emit
#pragma unroll
    for (int mt = 0; mt < 4; ++mt) {
        const int gmA = mBlock + wm * 64 + mt * 16 + (lane >> 2);
#pragma unroll
        for (int half = 0; half < 2; ++half) {
            const int gm = gmA + half * 8;
            float* orow = out + (size_t)gm * NCOLS;
#pragma unroll
            for (int nt = 0; nt < 4; ++nt) {
                const int gn = nBlock + wn * 32 + nt * 8 + (lane & 3) * 2;
                float v0 = acc[mt][nt][half * 2 + 0];
                float v1 = acc[mt][nt][half * 2 + 1];
                if constexpr (NCOLS % 128 == 0) {
                    v0 += __ldg(bias + gn);
                    v1 += __ldg(bias + gn + 1);
                    if (RELU) { v0 = fmaxf(v0, 0.f); v1 = fmaxf(v1, 0.f); }
                    *reinterpret_cast<float2*>(orow + gn) = make_float2(v0, v1);
                    if (WSPLIT && gm < split_rows) {
                        uint32_t h0 = __float_as_uint(v0) & 0xFFFF0000u;
                        uint32_t h1 = __float_as_uint(v1) & 0xFFFF0000u;
                        size_t so = (size_t)gm * (NCOLS / 2) + (gn >> 1);
                        sp_hi[so] = (h0 >> 16) | h1;
                        sp_lo[so] = cvt_bf16x2(v0 - __uint_as_float(h0),
                                               v1 - __uint_as_float(h1));
                    }
                } else {
                    if (gn < NCOLS) {
                        float v = v0 + __ldg(bias + gn);
                        if (RELU) v = fmaxf(v, 0.f);
                        orow[gn] = v;
                    }
                    if (gn + 1 < NCOLS) {
                        float v = v1 + __ldg(bias + gn + 1);
                        if (RELU) v = fmaxf(v, 0.f);
                        orow[gn + 1] = v;
                    }
                }
            }
        }
    }
}

// ======================== host launcher =====================================
static inline int cdiv_host(long long a, long long b) { return (int)((a + b - 1) / b); }

extern "C" void kernel_launch(void* const* d_in, const int* in_sizes, int n_in,
                              void* d_out, int out_size) {
    (void)in_sizes; (void)n_in; (void)out_size;
    const float* x   = (const float*)d_in[0];
    const int* es0   = (const int*)d_in[1];
    const int* ed0   = (const int*)d_in[2];
    const int* es1   = (const int*)d_in[3];
    const int* ed1   = (const int*)d_in[4];
    const int* es2   = (const int*)d_in[5];
    const int* ed2   = (const int*)d_in[6];
    const float* Ws0 = (const float*)d_in[7];
    const float* Wn0 = (const float*)d_in[8];
    const float* b0  = (const float*)d_in[9];
    const float* Ws1 = (const float*)d_in[10];
    const float* Wn1 = (const float*)d_in[11];
    const float* b1  = (const float*)d_in[12];
    const float* Ws2 = (const float*)d_in[13];
    const float* Wn2 = (const float*)d_in[14];
    const float* b2  = (const float*)d_in[15];
    float* out = (float*)d_out;

    float *agg0, *deg0, *h1, *agg1, *deg1, *h2, *agg2, *deg2;
    cudaGetSymbolAddress((void**)&agg0, g_agg0);
    cudaGetSymbolAddress((void**)&deg0, g_deg0);
    cudaGetSymbolAddress((void**)&h1,   g_h1);
    cudaGetSymbolAddress((void**)&agg1, g_agg1);
    cudaGetSymbolAddress((void**)&deg1, g_deg1);
    cudaGetSymbolAddress((void**)&h2,   g_h2);
    cudaGetSymbolAddress((void**)&agg2, g_agg2);
    cudaGetSymbolAddress((void**)&deg2, g_deg2);

    __nv_bfloat16 *xs_hi, *xs_lo, *a0_hi, *a0_lo, *h1s_hi, *h1s_lo;
    __nv_bfloat16 *a1_hi, *a1_lo, *h2s_hi, *h2s_lo, *a2_hi, *a2_lo;
    cudaGetSymbolAddress((void**)&xs_hi, g_xs_hi);
    cudaGetSymbolAddress((void**)&xs_lo, g_xs_lo);
    cudaGetSymbolAddress((void**)&a0_hi, g_a0_hi);
    cudaGetSymbolAddress((void**)&a0_lo, g_a0_lo);
    cudaGetSymbolAddress((void**)&h1s_hi, g_h1s_hi);
    cudaGetSymbolAddress((void**)&h1s_lo, g_h1s_lo);
    cudaGetSymbolAddress((void**)&a1_hi, g_a1_hi);
    cudaGetSymbolAddress((void**)&a1_lo, g_a1_lo);
    cudaGetSymbolAddress((void**)&h2s_hi, g_h2s_hi);
    cudaGetSymbolAddress((void**)&h2s_lo, g_h2s_lo);
    cudaGetSymbolAddress((void**)&a2_hi, g_a2_hi);
    cudaGetSymbolAddress((void**)&a2_lo, g_a2_lo);
    __nv_bfloat16 *w0h, *w0l, *w1h, *w1l, *w2h, *w2l;
    cudaGetSymbolAddress((void**)&w0h, g_w0_hi);
    cudaGetSymbolAddress((void**)&w0l, g_w0_lo);
    cudaGetSymbolAddress((void**)&w1h, g_w1_hi);
    cudaGetSymbolAddress((void**)&w1l, g_w1_lo);
    cudaGetSymbolAddress((void**)&w2h, g_w2_hi);
    cudaGetSymbolAddress((void**)&w2l, g_w2_lo);

    const int T = 256;
    constexpr int SMEM_SZ = 2 * (128 * 72 * 2) + 2 * (64 * 136 * 2);  // 71680

    cudaFuncSetAttribute(gemm_mma<128, 256, 256, true, true>,
                         cudaFuncAttributeMaxDynamicSharedMemorySize, SMEM_SZ);
    cudaFuncSetAttribute(gemm_mma<256, 256, 256, true, true>,
                         cudaFuncAttributeMaxDynamicSharedMemorySize, SMEM_SZ);
    cudaFuncSetAttribute(gemm_mma<256, 47, 128, false, false>,
                         cudaFuncAttributeMaxDynamicSharedMemorySize, SMEM_SZ);

    // ---- weight prep + x split (independent of scatters)
    prep_w<100, 256, 128, 256><<<cdiv_host(2 * 128 * 256, T), T>>>(Ws0, Wn0, w0h, w0l);
    prep_w<256, 256, 256, 256><<<cdiv_host(2 * 256 * 256, T), T>>>(Ws1, Wn1, w1h, w1l);
    prep_w<256, 47, 256, 128><<<cdiv_host(2 * 256 * 128, T), T>>>(Ws2, Wn2, w2h, w2l);
    split_kern<100, 128, false><<<cdiv_host((long long)kN1 * 32, T), T>>>(
        x, nullptr, kN1, (uint2*)xs_hi, (uint2*)xs_lo);

    // ---------------- layer 0: x[1M,100] -> h1[262144,256]
    {
        int n4a = kN1 * kF / 4, n4d = kN1 / 4;
        zero_kern<<<cdiv_host(n4a, T), T>>>((float4*)agg0, n4a);
        zero_kern<<<cdiv_host(n4d, T), T>>>((float4*)deg0, n4d);
        scatter_kern<kF><<<cdiv_host((long long)kE0 * 32, T), T>>>(x, es0, ed0, kE0, agg0, deg0);
        split_kern<100, 128, true><<<cdiv_host((long long)kN1 * 32, T), T>>>(
            agg0, deg0, kN1, (uint2*)a0_hi, (uint2*)a0_lo);
        gemm_mma<128, 256, 256, true, true><<<dim3(kN1 / 128, 2), T, SMEM_SZ>>>(
            xs_hi, xs_lo, a0_hi, a0_lo, w0h, w0l, b0, h1,
            (uint32_t*)h1s_hi, (uint32_t*)h1s_lo, kN2);
    }
    // ---------------- layer 1: h1 -> h2[32768,256]
    {
        int n4a = kN2 * kH / 4, n4d = kN2 / 4;
        zero_kern<<<cdiv_host(n4a, T), T>>>((float4*)agg1, n4a);
        zero_kern<<<cdiv_host(n4d, T), T>>>((float4*)deg1, n4d);
        scatter_kern<kH><<<cdiv_host((long long)kE1 * 32, T), T>>>(h1, es1, ed1, kE1, agg1, deg1);
        split_kern<256, 256, true><<<cdiv_host((long long)kN2 * 64, T), T>>>(
            agg1, deg1, kN2, (uint2*)a1_hi, (uint2*)a1_lo);
        gemm_mma<256, 256, 256, true, true><<<dim3(kN2 / 128, 2), T, SMEM_SZ>>>(
            h1s_hi, h1s_lo, a1_hi, a1_lo, w1h, w1l, b1, h2,
            (uint32_t*)h2s_hi, (uint32_t*)h2s_lo, kN3);
    }
    // ---------------- layer 2: h2 -> out[8192,47]
    {
        int n4a = kN3 * kH / 4, n4d = kN3 / 4;
        zero_kern<<<cdiv_host(n4a, T), T>>>((float4*)agg2, n4a);
        zero_kern<<<cdiv_host(n4d, T), T>>>((float4*)deg2, n4d);
        scatter_kern<kH><<<cdiv_host((long long)kE2 * 32, T), T>>>(h2, es2, ed2, kE2, agg2, deg2);
        split_kern<256, 256, true><<<cdiv_host((long long)kN3 * 64, T), T>>>(
            agg2, deg2, kN3, (uint2*)a2_hi, (uint2*)a2_lo);
        gemm_mma<256, 47, 128, false, false><<<dim3(kN3 / 128, 1), T, SMEM_SZ>>>(
            h2s_hi, h2s_lo, a2_hi, a2_lo, w2h, w2l, b2, out,
            nullptr, nullptr, 0);
    }
}

// round 5
// speedup vs baseline: 1.8944x; 1.2832x over previous
#include <cuda_runtime.h>
#include <cuda_bf16.h>
#include <cstdint>
#include <cstddef>

// ---------------------------------------------------------------------------
// SAGE 3-layer GraphSAGE. Per layer:
//   zero agg/deg -> edge scatter (red.v4.f32) -> split agg to bf16 hi/lo with
//   fused 1/deg scaling -> cp.async-pipelined mma.sync bf16x3 dual GEMM with
//   bias+relu epilogue that also emits the next layer's self-operand split.
// R5 fix: A-tile cp.async loader covers all 8 octets per row (4 contiguous
// 16B copies per thread per plane); R4 left half the row unloaded and read
// out of bounds on the last row/chunk.
// ---------------------------------------------------------------------------

namespace {
constexpr int kN1 = 262144, kN2 = 32768, kN3 = 8192;
constexpr int kE0 = 1310720, kE1 = 327680, kE2 = 81920;
constexpr int kF = 100, kH = 256, kC = 47;
}  // namespace

// -------- fp32 scratch ------------------------------------------------------
__device__ float g_agg0[(size_t)kN1 * kF];
__device__ float g_deg0[kN1];
__device__ float g_h1[(size_t)kN1 * kH];
__device__ float g_agg1[(size_t)kN2 * kH];
__device__ float g_deg1[kN2];
__device__ float g_h2[(size_t)kN2 * kH];
__device__ float g_agg2[(size_t)kN3 * kH];
__device__ float g_deg2[kN3];

// -------- bf16 split operand buffers (K padded to 128/256) ------------------
__device__ __nv_bfloat16 g_xs_hi[(size_t)kN1 * 128], g_xs_lo[(size_t)kN1 * 128];
__device__ __nv_bfloat16 g_a0_hi[(size_t)kN1 * 128], g_a0_lo[(size_t)kN1 * 128];
__device__ __nv_bfloat16 g_h1s_hi[(size_t)kN2 * 256], g_h1s_lo[(size_t)kN2 * 256];
__device__ __nv_bfloat16 g_a1_hi[(size_t)kN2 * 256], g_a1_lo[(size_t)kN2 * 256];
__device__ __nv_bfloat16 g_h2s_hi[(size_t)kN3 * 256], g_h2s_lo[(size_t)kN3 * 256];
__device__ __nv_bfloat16 g_a2_hi[(size_t)kN3 * 256], g_a2_lo[(size_t)kN3 * 256];

// -------- pre-split weights: [2 phases][KPAD][NPAD] -------------------------
__device__ __nv_bfloat16 g_w0_hi[2 * 128 * 256], g_w0_lo[2 * 128 * 256];
__device__ __nv_bfloat16 g_w1_hi[2 * 256 * 256], g_w1_lo[2 * 256 * 256];
__device__ __nv_bfloat16 g_w2_hi[2 * 256 * 128], g_w2_lo[2 * 256 * 128];

// ======================== PTX helpers (arch-agnostic) ========================
__device__ __forceinline__ uint32_t smem_u32(const void* p) {
    return (uint32_t)__cvta_generic_to_shared(p);
}
__device__ __forceinline__ void ldsm4(uint32_t* r, uint32_t addr) {
    asm volatile("ldmatrix.sync.aligned.m8n8.x4.shared.b16 {%0,%1,%2,%3}, [%4];"
                 : "=r"(r[0]), "=r"(r[1]), "=r"(r[2]), "=r"(r[3]) : "r"(addr));
}
__device__ __forceinline__ void ldsm4t(uint32_t* r, uint32_t addr) {
    asm volatile("ldmatrix.sync.aligned.m8n8.x4.trans.shared.b16 {%0,%1,%2,%3}, [%4];"
                 : "=r"(r[0]), "=r"(r[1]), "=r"(r[2]), "=r"(r[3]) : "r"(addr));
}
__device__ __forceinline__ void mma_bf16(float* d, const uint32_t* a,
                                         uint32_t b0, uint32_t b1) {
    asm volatile(
        "mma.sync.aligned.m16n8k16.row.col.f32.bf16.bf16.f32 "
        "{%0,%1,%2,%3}, {%4,%5,%6,%7}, {%8,%9}, {%0,%1,%2,%3};"
        : "+f"(d[0]), "+f"(d[1]), "+f"(d[2]), "+f"(d[3])
        : "r"(a[0]), "r"(a[1]), "r"(a[2]), "r"(a[3]), "r"(b0), "r"(b1));
}
__device__ __forceinline__ uint32_t cvt_bf16x2(float a, float b) {
    uint32_t r;
    asm("cvt.rn.bf16x2.f32 %0, %1, %2;" : "=r"(r) : "f"(b), "f"(a));
    return r;
}
__device__ __forceinline__ void cp_async16(uint32_t saddr, const void* gptr) {
    asm volatile("cp.async.ca.shared.global [%0], [%1], 16;"
                 :: "r"(saddr), "l"(gptr));
}
#define CP_COMMIT() asm volatile("cp.async.commit_group;" ::: "memory")

// ======================== small kernels =====================================
__global__ void zero_kern(float4* __restrict__ p, int n4) {
    int i = blockIdx.x * blockDim.x + threadIdx.x;
    int stride = gridDim.x * blockDim.x;
    float4 z = make_float4(0.f, 0.f, 0.f, 0.f);
    for (; i < n4; i += stride) p[i] = z;
}

// One warp per edge; vector red quarters the L2 atomic op count.
template <int K>
__global__ void scatter_kern(const float* __restrict__ feat,
                             const int* __restrict__ esrc,
                             const int* __restrict__ edst, int nE,
                             float* __restrict__ agg, float* __restrict__ deg) {
    int warp = (blockIdx.x * blockDim.x + threadIdx.x) >> 5;
    int lane = threadIdx.x & 31;
    if (warp >= nE) return;
    int s = __ldg(esrc + warp);
    int d = __ldg(edst + warp);
    const float4* src = reinterpret_cast<const float4*>(feat + (size_t)s * K);
    float* dst = agg + (size_t)d * K;
    constexpr int NV = K / 4;
#pragma unroll
    for (int v = lane; v < NV; v += 32) {
        float4 f = __ldg(src + v);
        asm volatile("red.global.add.v4.f32 [%0], {%1, %2, %3, %4};"
                     :: "l"(dst + 4 * v), "f"(f.x), "f"(f.y), "f"(f.z), "f"(f.w)
                     : "memory");
    }
    if (lane == 31) atomicAdd(deg + d, 1.0f);
}

// Split fp32 -> bf16 hi (bit-truncation) + lo (RN remainder), zero-padded K.
template <int K, int KPAD, bool SCALE>
__global__ void split_kern(const float* __restrict__ in,
                           const float* __restrict__ deg, int rows,
                           uint2* __restrict__ hi, uint2* __restrict__ lo) {
    constexpr int PR = KPAD / 4;
    int idx = blockIdx.x * blockDim.x + threadIdx.x;
    if (idx >= rows * PR) return;
    int row = idx / PR, kq = idx % PR;
    int k4 = kq * 4;
    float4 v = make_float4(0.f, 0.f, 0.f, 0.f);
    if (k4 < K)
        v = *reinterpret_cast<const float4*>(in + (size_t)row * K + k4);
    if (SCALE) {
        float r = 1.f / fmaxf(__ldg(deg + row), 1.f);
        v.x *= r; v.y *= r; v.z *= r; v.w *= r;
    }
    uint32_t hx = __float_as_uint(v.x) & 0xFFFF0000u;
    uint32_t hy = __float_as_uint(v.y) & 0xFFFF0000u;
    uint32_t hz = __float_as_uint(v.z) & 0xFFFF0000u;
    uint32_t hw = __float_as_uint(v.w) & 0xFFFF0000u;
    uint2 ho, lv;
    ho.x = (hx >> 16) | hy;
    ho.y = (hz >> 16) | hw;
    lv.x = cvt_bf16x2(v.x - __uint_as_float(hx), v.y - __uint_as_float(hy));
    lv.y = cvt_bf16x2(v.z - __uint_as_float(hz), v.w - __uint_as_float(hw));
    size_t o = (size_t)row * PR + kq;
    hi[o] = ho;
    lo[o] = lv;
}

// Pre-split weights into [2][KPAD][NPAD] bf16 hi/lo with zero padding.
template <int K1, int NCOLS, int KPAD, int NPAD>
__global__ void prep_w(const float* __restrict__ Ws, const float* __restrict__ Wn,
                       __nv_bfloat16* __restrict__ hi, __nv_bfloat16* __restrict__ lo) {
    int idx = blockIdx.x * blockDim.x + threadIdx.x;
    constexpr int TOT = 2 * KPAD * NPAD;
    if (idx >= TOT) return;
    int phase = idx / (KPAD * NPAD);
    int rem = idx % (KPAD * NPAD);
    int k = rem / NPAD, n = rem % NPAD;
    float v = 0.f;
    if (k < K1 && n < NCOLS) v = (phase ? Wn : Ws)[(size_t)k * NCOLS + n];
    uint32_t h = __float_as_uint(v) & 0xFFFF0000u;
    hi[idx] = __ushort_as_bfloat16((unsigned short)(h >> 16));
    lo[idx] = __float2bfloat16(v - __uint_as_float(h));
}

// ======================== cp.async pipelined bf16x3 GEMM =====================
// Block tile 128(m) x 128(n) x 64(k), 2-stage cp.async double buffer,
// 8 warps of 64x32, grid = (n-tiles, m-tiles) so n-tiles sharing A are
// launch-adjacent (L2 reuse of A).
template <int KPAD, int NCOLS, int NPAD, bool RELU, bool WSPLIT>
__global__ void __launch_bounds__(256, 1)
gemm_mma(const __nv_bfloat16* __restrict__ As_hi, const __nv_bfloat16* __restrict__ As_lo,
         const __nv_bfloat16* __restrict__ An_hi, const __nv_bfloat16* __restrict__ An_lo,
         const __nv_bfloat16* __restrict__ W_hi, const __nv_bfloat16* __restrict__ W_lo,
         const float* __restrict__ bias, float* __restrict__ out,
         uint32_t* __restrict__ sp_hi, uint32_t* __restrict__ sp_lo, int split_rows) {
    constexpr int BK = 64;
    constexpr int AST = 72;                 // A smem row stride (bf16)
    constexpr int BST = 136;                // B smem row stride (bf16)
    constexpr int ABYTES = 128 * AST * 2;   // 18432
    constexpr int BBYTES = BK * BST * 2;    // 17408
    constexpr int SSTRIDE = 2 * ABYTES + 2 * BBYTES;  // 71680 per stage
    constexpr int CPP = KPAD / BK;
    constexpr int NCH = 2 * CPP;

    extern __shared__ char smem[];
    const uint32_t su = smem_u32(smem);

    const int tid = threadIdx.x;
    const int lane = tid & 31, wid = tid >> 5;
    const int wm = wid & 1, wn = wid >> 1;   // warp grid 2(m) x 4(n)
    const int nBlock = blockIdx.x * 128, mBlock = blockIdx.y * 128;

    // per-thread load geometry
    const int ar = tid >> 1;                 // A row (2 thr/row)
    const int ab = (tid & 1) * 64;           // A byte base within 128B row half
    const int br = tid >> 4;                 // B row base (16 thr/row)
    const int bc = tid & 15;                 // B col-octet

    auto issue_chunk = [&](int c) {
        const int stage = c & 1;
        const int phase = c / CPP;
        const int k0 = (c % CPP) * BK;
        const __nv_bfloat16* Ahi = phase ? An_hi : As_hi;
        const __nv_bfloat16* Alo = phase ? An_lo : As_lo;
        const uint32_t sb = su + stage * SSTRIDE;
        // A hi/lo: 128 rows x 64 bf16 = 128B/row; thread covers 64 contiguous
        // bytes (4 x 16B) of its row half, per plane.
        {
            size_t g = (size_t)(mBlock + ar) * KPAD + k0 + ab / 2;  // bf16 elems
            uint32_t sa = sb + 2u * (uint32_t)(ar * AST) + (uint32_t)ab;
#pragma unroll
            for (int q = 0; q < 4; ++q) {
                cp_async16(sa + 16 * q, Ahi + g + 8 * q);
                cp_async16(sa + (uint32_t)ABYTES + 16 * q, Alo + g + 8 * q);
            }
        }
        // B hi/lo: 64 rows x 128 bf16; 16 thr/row, one 16B octet, 4 row groups
        {
            const __nv_bfloat16* wb =
                W_hi + (size_t)phase * KPAD * NPAD + (size_t)k0 * NPAD + nBlock;
            const __nv_bfloat16* wl =
                W_lo + (size_t)phase * KPAD * NPAD + (size_t)k0 * NPAD + nBlock;
#pragma unroll
            for (int it = 0; it < 4; ++it) {
                int r = br + it * 16;
                size_t g = (size_t)r * NPAD + bc * 8;
                uint32_t sbb = sb + 2u * (uint32_t)ABYTES +
                               2u * (uint32_t)(r * BST + bc * 8);
                cp_async16(sbb, wb + g);
                cp_async16(sbb + (uint32_t)BBYTES, wl + g);
            }
        }
        CP_COMMIT();
    };

    float acc[4][4][4];
#pragma unroll
    for (int i = 0; i < 4; i++)
#pragma unroll
        for (int j = 0; j < 4; j++)
#pragma unroll
            for (int r = 0; r < 4; r++) acc[i][j][r] = 0.f;

    // ldmatrix lane geometry
    const int lr = lane & 15;
    const int lc = (lane >> 4) * 8;
    const uint32_t aOff = 2u * (uint32_t)((wm * 64 + lr) * AST + lc);
    const uint32_t bOff = 2u * (uint32_t)ABYTES + 2u * (uint32_t)(lr * BST + wn * 32 + lc);

    issue_chunk(0);
    for (int c = 0; c < NCH; ++c) {
        if (c + 1 < NCH) {
            issue_chunk(c + 1);
            asm volatile("cp.async.wait_group 1;" ::: "memory");
        } else {
            asm volatile("cp.async.wait_group 0;" ::: "memory");
        }
        __syncthreads();
        const uint32_t sb = su + (c & 1) * SSTRIDE;
        const uint32_t aHiBase = sb + aOff;
        const uint32_t bHiBase = sb + bOff;
#pragma unroll
        for (int k16 = 0; k16 < BK / 16; ++k16) {
            const uint32_t kk = k16 * 16;
            uint32_t ah[4][4], bh[2][4];
#pragma unroll
            for (int p = 0; p < 2; ++p)
                ldsm4t(bh[p], bHiBase + 2u * (kk * BST + p * 16));
#pragma unroll
            for (int mt = 0; mt < 4; ++mt)
                ldsm4(ah[mt], aHiBase + 2u * (mt * 16 * AST + kk));
#pragma unroll
            for (int mt = 0; mt < 4; ++mt)
#pragma unroll
                for (int nt = 0; nt < 4; ++nt)
                    mma_bf16(acc[mt][nt], ah[mt], bh[nt >> 1][(nt & 1) * 2],
                             bh[nt >> 1][(nt & 1) * 2 + 1]);
            {   // hi*lo
                uint32_t bl[2][4];
#pragma unroll
                for (int p = 0; p < 2; ++p)
                    ldsm4t(bl[p], bHiBase + (uint32_t)BBYTES + 2u * (kk * BST + p * 16));
#pragma unroll
                for (int mt = 0; mt < 4; ++mt)
#pragma unroll
                    for (int nt = 0; nt < 4; ++nt)
                        mma_bf16(acc[mt][nt], ah[mt], bl[nt >> 1][(nt & 1) * 2],
                                 bl[nt >> 1][(nt & 1) * 2 + 1]);
            }
            {   // lo*hi
                uint32_t al[4][4];
#pragma unroll
                for (int mt = 0; mt < 4; ++mt)
                    ldsm4(al[mt], aHiBase + (uint32_t)ABYTES + 2u * (mt * 16 * AST + kk));
#pragma unroll
                for (int mt = 0; mt < 4; ++mt)
#pragma unroll
                    for (int nt = 0; nt < 4; ++nt)
                        mma_bf16(acc[mt][nt], al[mt], bh[nt >> 1][(nt & 1) * 2],
                                 bh[nt >> 1][(nt & 1) * 2 + 1]);
            }
        }
        __syncthreads();  // protect stage buffer before it is re-filled
    }

    // ---- epilogue: bias (+relu), store fp32, optional bf16 split emit
#pragma unroll
    for (int mt = 0; mt < 4; ++mt) {
        const int gmA = mBlock + wm * 64 + mt * 16 + (lane >> 2);
#pragma unroll
        for (int half = 0; half < 2; ++half) {
            const int gm = gmA + half * 8;
            float* orow = out + (size_t)gm * NCOLS;
#pragma unroll
            for (int nt = 0; nt < 4; ++nt) {
                const int gn = nBlock + wn * 32 + nt * 8 + (lane & 3) * 2;
                float v0 = acc[mt][nt][half * 2 + 0];
                float v1 = acc[mt][nt][half * 2 + 1];
                if constexpr (NCOLS % 128 == 0) {
                    v0 += __ldg(bias + gn);
                    v1 += __ldg(bias + gn + 1);
                    if (RELU) { v0 = fmaxf(v0, 0.f); v1 = fmaxf(v1, 0.f); }
                    *reinterpret_cast<float2*>(orow + gn) = make_float2(v0, v1);
                    if (WSPLIT && gm < split_rows) {
                        uint32_t h0 = __float_as_uint(v0) & 0xFFFF0000u;
                        uint32_t h1 = __float_as_uint(v1) & 0xFFFF0000u;
                        size_t so = (size_t)gm * (NCOLS / 2) + (gn >> 1);
                        sp_hi[so] = (h0 >> 16) | h1;
                        sp_lo[so] = cvt_bf16x2(v0 - __uint_as_float(h0),
                                               v1 - __uint_as_float(h1));
                    }
                } else {
                    if (gn < NCOLS) {
                        float v = v0 + __ldg(bias + gn);
                        if (RELU) v = fmaxf(v, 0.f);
                        orow[gn] = v;
                    }
                    if (gn + 1 < NCOLS) {
                        float v = v1 + __ldg(bias + gn + 1);
                        if (RELU) v = fmaxf(v, 0.f);
                        orow[gn + 1] = v;
                    }
                }
            }
        }
    }
}

// ======================== host launcher =====================================
static inline int cdiv_host(long long a, long long b) { return (int)((a + b - 1) / b); }

extern "C" void kernel_launch(void* const* d_in, const int* in_sizes, int n_in,
                              void* d_out, int out_size) {
    (void)in_sizes; (void)n_in; (void)out_size;
    const float* x   = (const float*)d_in[0];
    const int* es0   = (const int*)d_in[1];
    const int* ed0   = (const int*)d_in[2];
    const int* es1   = (const int*)d_in[3];
    const int* ed1   = (const int*)d_in[4];
    const int* es2   = (const int*)d_in[5];
    const int* ed2   = (const int*)d_in[6];
    const float* Ws0 = (const float*)d_in[7];
    const float* Wn0 = (const float*)d_in[8];
    const float* b0  = (const float*)d_in[9];
    const float* Ws1 = (const float*)d_in[10];
    const float* Wn1 = (const float*)d_in[11];
    const float* b1  = (const float*)d_in[12];
    const float* Ws2 = (const float*)d_in[13];
    const float* Wn2 = (const float*)d_in[14];
    const float* b2  = (const float*)d_in[15];
    float* out = (float*)d_out;

    float *agg0, *deg0, *h1, *agg1, *deg1, *h2, *agg2, *deg2;
    cudaGetSymbolAddress((void**)&agg0, g_agg0);
    cudaGetSymbolAddress((void**)&deg0, g_deg0);
    cudaGetSymbolAddress((void**)&h1,   g_h1);
    cudaGetSymbolAddress((void**)&agg1, g_agg1);
    cudaGetSymbolAddress((void**)&deg1, g_deg1);
    cudaGetSymbolAddress((void**)&h2,   g_h2);
    cudaGetSymbolAddress((void**)&agg2, g_agg2);
    cudaGetSymbolAddress((void**)&deg2, g_deg2);

    __nv_bfloat16 *xs_hi, *xs_lo, *a0_hi, *a0_lo, *h1s_hi, *h1s_lo;
    __nv_bfloat16 *a1_hi, *a1_lo, *h2s_hi, *h2s_lo, *a2_hi, *a2_lo;
    cudaGetSymbolAddress((void**)&xs_hi, g_xs_hi);
    cudaGetSymbolAddress((void**)&xs_lo, g_xs_lo);
    cudaGetSymbolAddress((void**)&a0_hi, g_a0_hi);
    cudaGetSymbolAddress((void**)&a0_lo, g_a0_lo);
    cudaGetSymbolAddress((void**)&h1s_hi, g_h1s_hi);
    cudaGetSymbolAddress((void**)&h1s_lo, g_h1s_lo);
    cudaGetSymbolAddress((void**)&a1_hi, g_a1_hi);
    cudaGetSymbolAddress((void**)&a1_lo, g_a1_lo);
    cudaGetSymbolAddress((void**)&h2s_hi, g_h2s_hi);
    cudaGetSymbolAddress((void**)&h2s_lo, g_h2s_lo);
    cudaGetSymbolAddress((void**)&a2_hi, g_a2_hi);
    cudaGetSymbolAddress((void**)&a2_lo, g_a2_lo);
    __nv_bfloat16 *w0h, *w0l, *w1h, *w1l, *w2h, *w2l;
    cudaGetSymbolAddress((void**)&w0h, g_w0_hi);
    cudaGetSymbolAddress((void**)&w0l, g_w0_lo);
    cudaGetSymbolAddress((void**)&w1h, g_w1_hi);
    cudaGetSymbolAddress((void**)&w1l, g_w1_lo);
    cudaGetSymbolAddress((void**)&w2h, g_w2_hi);
    cudaGetSymbolAddress((void**)&w2l, g_w2_lo);

    const int T = 256;
    constexpr int SMEM_SZ = 2 * (2 * 128 * 72 * 2 + 2 * 64 * 136 * 2);  // 143360

    cudaFuncSetAttribute(gemm_mma<128, 256, 256, true, true>,
                         cudaFuncAttributeMaxDynamicSharedMemorySize, SMEM_SZ);
    cudaFuncSetAttribute(gemm_mma<256, 256, 256, true, true>,
                         cudaFuncAttributeMaxDynamicSharedMemorySize, SMEM_SZ);
    cudaFuncSetAttribute(gemm_mma<256, 47, 128, false, false>,
                         cudaFuncAttributeMaxDynamicSharedMemorySize, SMEM_SZ);

    // ---- weight prep + x split (independent of scatters)
    prep_w<100, 256, 128, 256><<<cdiv_host(2 * 128 * 256, T), T>>>(Ws0, Wn0, w0h, w0l);
    prep_w<256, 256, 256, 256><<<cdiv_host(2 * 256 * 256, T), T>>>(Ws1, Wn1, w1h, w1l);
    prep_w<256, 47, 256, 128><<<cdiv_host(2 * 256 * 128, T), T>>>(Ws2, Wn2, w2h, w2l);
    split_kern<100, 128, false><<<cdiv_host((long long)kN1 * 32, T), T>>>(
        x, nullptr, kN1, (uint2*)xs_hi, (uint2*)xs_lo);

    // ---------------- layer 0: x[1M,100] -> h1[262144,256]
    {
        int n4a = kN1 * kF / 4, n4d = kN1 / 4;
        zero_kern<<<cdiv_host(n4a, T), T>>>((float4*)agg0, n4a);
        zero_kern<<<cdiv_host(n4d, T), T>>>((float4*)deg0, n4d);
        scatter_kern<kF><<<cdiv_host((long long)kE0 * 32, T), T>>>(x, es0, ed0, kE0, agg0, deg0);
        split_kern<100, 128, true><<<cdiv_host((long long)kN1 * 32, T), T>>>(
            agg0, deg0, kN1, (uint2*)a0_hi, (uint2*)a0_lo);
        gemm_mma<128, 256, 256, true, true><<<dim3(2, kN1 / 128), T, SMEM_SZ>>>(
            xs_hi, xs_lo, a0_hi, a0_lo, w0h, w0l, b0, h1,
            (uint32_t*)h1s_hi, (uint32_t*)h1s_lo, kN2);
    }
    // ---------------- layer 1: h1 -> h2[32768,256]
    {
        int n4a = kN2 * kH / 4, n4d = kN2 / 4;
        zero_kern<<<cdiv_host(n4a, T), T>>>((float4*)agg1, n4a);
        zero_kern<<<cdiv_host(n4d, T), T>>>((float4*)deg1, n4d);
        scatter_kern<kH><<<cdiv_host((long long)kE1 * 32, T), T>>>(h1, es1, ed1, kE1, agg1, deg1);
        split_kern<256, 256, true><<<cdiv_host((long long)kN2 * 64, T), T>>>(
            agg1, deg1, kN2, (uint2*)a1_hi, (uint2*)a1_lo);
        gemm_mma<256, 256, 256, true, true><<<dim3(2, kN2 / 128), T, SMEM_SZ>>>(
            h1s_hi, h1s_lo, a1_hi, a1_lo, w1h, w1l, b1, h2,
            (uint32_t*)h2s_hi, (uint32_t*)h2s_lo, kN3);
    }
    // ---------------- layer 2: h2 -> out[8192,47]
    {
        int n4a = kN3 * kH / 4, n4d = kN3 / 4;
        zero_kern<<<cdiv_host(n4a, T), T>>>((float4*)agg2, n4a);
        zero_kern<<<cdiv_host(n4d, T), T>>>((float4*)deg2, n4d);
        scatter_kern<kH><<<cdiv_host((long long)kE2 * 32, T), T>>>(h2, es2, ed2, kE2, agg2, deg2);
        split_kern<256, 256, true><<<cdiv_host((long long)kN3 * 64, T), T>>>(
            agg2, deg2, kN3, (uint2*)a2_hi, (uint2*)a2_lo);
        gemm_mma<256, 47, 128, false, false><<<dim3(1, kN3 / 128), T, SMEM_SZ>>>(
            h2s_hi, h2s_lo, a2_hi, a2_lo, w2h, w2l, b2, out,
            nullptr, nullptr, 0);
    }
}

// round 6
// speedup vs baseline: 2.2344x; 1.1795x over previous
#include <cuda_runtime.h>
#include <cuda_bf16.h>
#include <cstdint>
#include <cstddef>

// ---------------------------------------------------------------------------
// SAGE 3-layer GraphSAGE. Per layer:
//   CSC bucket build (count -> block-scan reserve -> fill) ->
//   warp-per-dst gather-mean that writes bf16 hi/lo splits directly ->
//   cp.async-pipelined mma.sync bf16x3 dual GEMM (bias+relu epilogue that
//   also emits next layer's self-operand split).
// R6: atomic feature scatter + agg zero + split_agg replaced by atomic-free
// gather aggregation (only cheap int atomics remain).
// ---------------------------------------------------------------------------

namespace {
constexpr int kN1 = 262144, kN2 = 32768, kN3 = 8192;
constexpr int kE0 = 1310720, kE1 = 327680, kE2 = 81920;
constexpr int kF = 100, kH = 256, kC = 47;
}  // namespace

// -------- fp32 activations (gather sources) ---------------------------------
__device__ float g_h1[(size_t)kN1 * kH];
__device__ float g_h2[(size_t)kN2 * kH];

// -------- CSC scratch --------------------------------------------------------
__device__ int g_cnt[kN1];
__device__ int g_cur[kN1];
__device__ int g_off[kN1];
__device__ int g_cursor[1];
__device__ int g_csc[kE0];

// -------- bf16 split operand buffers (K padded to 128/256) ------------------
__device__ __nv_bfloat16 g_xs_hi[(size_t)kN1 * 128], g_xs_lo[(size_t)kN1 * 128];
__device__ __nv_bfloat16 g_a0_hi[(size_t)kN1 * 128], g_a0_lo[(size_t)kN1 * 128];
__device__ __nv_bfloat16 g_h1s_hi[(size_t)kN2 * 256], g_h1s_lo[(size_t)kN2 * 256];
__device__ __nv_bfloat16 g_a1_hi[(size_t)kN2 * 256], g_a1_lo[(size_t)kN2 * 256];
__device__ __nv_bfloat16 g_h2s_hi[(size_t)kN3 * 256], g_h2s_lo[(size_t)kN3 * 256];
__device__ __nv_bfloat16 g_a2_hi[(size_t)kN3 * 256], g_a2_lo[(size_t)kN3 * 256];

// -------- pre-split weights: [2 phases][KPAD][NPAD] -------------------------
__device__ __nv_bfloat16 g_w0_hi[2 * 128 * 256], g_w0_lo[2 * 128 * 256];
__device__ __nv_bfloat16 g_w1_hi[2 * 256 * 256], g_w1_lo[2 * 256 * 256];
__device__ __nv_bfloat16 g_w2_hi[2 * 256 * 128], g_w2_lo[2 * 256 * 128];

// ======================== PTX helpers (arch-agnostic) ========================
__device__ __forceinline__ uint32_t smem_u32(const void* p) {
    return (uint32_t)__cvta_generic_to_shared(p);
}
__device__ __forceinline__ void ldsm4(uint32_t* r, uint32_t addr) {
    asm volatile("ldmatrix.sync.aligned.m8n8.x4.shared.b16 {%0,%1,%2,%3}, [%4];"
                 : "=r"(r[0]), "=r"(r[1]), "=r"(r[2]), "=r"(r[3]) : "r"(addr));
}
__device__ __forceinline__ void ldsm4t(uint32_t* r, uint32_t addr) {
    asm volatile("ldmatrix.sync.aligned.m8n8.x4.trans.shared.b16 {%0,%1,%2,%3}, [%4];"
                 : "=r"(r[0]), "=r"(r[1]), "=r"(r[2]), "=r"(r[3]) : "r"(addr));
}
__device__ __forceinline__ void mma_bf16(float* d, const uint32_t* a,
                                         uint32_t b0, uint32_t b1) {
    asm volatile(
        "mma.sync.aligned.m16n8k16.row.col.f32.bf16.bf16.f32 "
        "{%0,%1,%2,%3}, {%4,%5,%6,%7}, {%8,%9}, {%0,%1,%2,%3};"
        : "+f"(d[0]), "+f"(d[1]), "+f"(d[2]), "+f"(d[3])
        : "r"(a[0]), "r"(a[1]), "r"(a[2]), "r"(a[3]), "r"(b0), "r"(b1));
}
__device__ __forceinline__ uint32_t cvt_bf16x2(float a, float b) {
    uint32_t r;
    asm("cvt.rn.bf16x2.f32 %0, %1, %2;" : "=r"(r) : "f"(b), "f"(a));
    return r;
}
__device__ __forceinline__ void cp_async16(uint32_t saddr, const void* gptr) {
    asm volatile("cp.async.ca.shared.global [%0], [%1], 16;"
                 :: "r"(saddr), "l"(gptr));
}
#define CP_COMMIT() asm volatile("cp.async.commit_group;" ::: "memory")

// ======================== CSC build kernels ==================================
__global__ void zero_int(int* __restrict__ p, int n) {
    int i = blockIdx.x * blockDim.x + threadIdx.x;
    if (i < n) p[i] = 0;
}
__global__ void count_kern(const int* __restrict__ edst, int nE,
                           int* __restrict__ cnt) {
    int i = blockIdx.x * blockDim.x + threadIdx.x;
    if (i < nE) atomicAdd(cnt + __ldg(edst + i), 1);
}
// Block-scan reservation: one global atomic per 256 counts.
__global__ void reserve_kern(const int* __restrict__ cnt, int* __restrict__ off,
                             int n, int* __restrict__ cursor) {
    __shared__ int s[256];
    __shared__ int base;
    int tid = threadIdx.x;
    int i = blockIdx.x * 256 + tid;
    int v = (i < n) ? __ldg(cnt + i) : 0;
    s[tid] = v;
    __syncthreads();
#pragma unroll
    for (int d = 1; d < 256; d <<= 1) {
        int t = (tid >= d) ? s[tid - d] : 0;
        __syncthreads();
        s[tid] += t;
        __syncthreads();
    }
    if (tid == 255) base = atomicAdd(cursor, s[255]);
    __syncthreads();
    if (i < n) off[i] = base + s[tid] - v;
}
__global__ void fill_kern(const int* __restrict__ esrc, const int* __restrict__ edst,
                          int nE, const int* __restrict__ off,
                          int* __restrict__ cur, int* __restrict__ csc) {
    int i = blockIdx.x * blockDim.x + threadIdx.x;
    if (i >= nE) return;
    int d = __ldg(edst + i);
    int p = atomicAdd(cur + d, 1);
    csc[__ldg(off + d) + p] = __ldg(esrc + i);
}

// ======================== gather-mean + split ================================
// Warp per dst row: sum incoming neighbor rows in registers, mean, write
// bf16 hi/lo split (zero-padded K -> KPAD). Atomic-free.
template <int K, int KPAD>
__global__ void gather_split(const float* __restrict__ feat,
                             const int* __restrict__ off,
                             const int* __restrict__ cnt,
                             const int* __restrict__ csc, int ndst,
                             uint2* __restrict__ hi, uint2* __restrict__ lo) {
    constexpr int NV = K / 4;                // float4 cols with data (25 / 64)
    constexpr int PV = KPAD / 4;             // padded float4 cols (32 / 64)
    constexpr int PER = (PV + 31) / 32;      // float4 cols per lane (1 / 2)
    int d = (blockIdx.x * blockDim.x + threadIdx.x) >> 5;
    int lane = threadIdx.x & 31;
    if (d >= ndst) return;
    int o0 = __ldg(off + d);
    int deg = __ldg(cnt + d);
    float4 acc[PER];
#pragma unroll
    for (int p = 0; p < PER; ++p) acc[p] = make_float4(0.f, 0.f, 0.f, 0.f);
    for (int e = 0; e < deg; ++e) {
        int s = __ldg(csc + o0 + e);
        const float4* row = reinterpret_cast<const float4*>(feat + (size_t)s * K);
#pragma unroll
        for (int p = 0; p < PER; ++p) {
            int v = lane + 32 * p;
            if (v < NV) {
                float4 f = __ldg(row + v);
                acc[p].x += f.x; acc[p].y += f.y; acc[p].z += f.z; acc[p].w += f.w;
            }
        }
    }
    float r = 1.f / fmaxf((float)deg, 1.f);
#pragma unroll
    for (int p = 0; p < PER; ++p) {
        int v = lane + 32 * p;
        if (v >= PV) continue;
        float4 w = make_float4(0.f, 0.f, 0.f, 0.f);
        if (v < NV) {
            w.x = acc[p].x * r; w.y = acc[p].y * r;
            w.z = acc[p].z * r; w.w = acc[p].w * r;
        }
        uint32_t hx = __float_as_uint(w.x) & 0xFFFF0000u;
        uint32_t hy = __float_as_uint(w.y) & 0xFFFF0000u;
        uint32_t hz = __float_as_uint(w.z) & 0xFFFF0000u;
        uint32_t hw = __float_as_uint(w.w) & 0xFFFF0000u;
        uint2 ho, lv;
        ho.x = (hx >> 16) | hy;
        ho.y = (hz >> 16) | hw;
        lv.x = cvt_bf16x2(w.x - __uint_as_float(hx), w.y - __uint_as_float(hy));
        lv.y = cvt_bf16x2(w.z - __uint_as_float(hz), w.w - __uint_as_float(hw));
        size_t oidx = (size_t)d * PV + v;
        hi[oidx] = ho;
        lo[oidx] = lv;
    }
}

// ======================== misc small kernels =================================
// Split fp32 -> bf16 hi/lo (for x self operand), zero-padded K.
template <int K, int KPAD>
__global__ void split_kern(const float* __restrict__ in, int rows,
                           uint2* __restrict__ hi, uint2* __restrict__ lo) {
    constexpr int PR = KPAD / 4;
    int idx = blockIdx.x * blockDim.x + threadIdx.x;
    if (idx >= rows * PR) return;
    int row = idx / PR, kq = idx % PR;
    int k4 = kq * 4;
    float4 v = make_float4(0.f, 0.f, 0.f, 0.f);
    if (k4 < K)
        v = *reinterpret_cast<const float4*>(in + (size_t)row * K + k4);
    uint32_t hx = __float_as_uint(v.x) & 0xFFFF0000u;
    uint32_t hy = __float_as_uint(v.y) & 0xFFFF0000u;
    uint32_t hz = __float_as_uint(v.z) & 0xFFFF0000u;
    uint32_t hw = __float_as_uint(v.w) & 0xFFFF0000u;
    uint2 ho, lv;
    ho.x = (hx >> 16) | hy;
    ho.y = (hz >> 16) | hw;
    lv.x = cvt_bf16x2(v.x - __uint_as_float(hx), v.y - __uint_as_float(hy));
    lv.y = cvt_bf16x2(v.z - __uint_as_float(hz), v.w - __uint_as_float(hw));
    size_t o = (size_t)row * PR + kq;
    hi[o] = ho;
    lo[o] = lv;
}

// Pre-split weights into [2][KPAD][NPAD] bf16 hi/lo with zero padding.
template <int K1, int NCOLS, int KPAD, int NPAD>
__global__ void prep_w(const float* __restrict__ Ws, const float* __restrict__ Wn,
                       __nv_bfloat16* __restrict__ hi, __nv_bfloat16* __restrict__ lo) {
    int idx = blockIdx.x * blockDim.x + threadIdx.x;
    constexpr int TOT = 2 * KPAD * NPAD;
    if (idx >= TOT) return;
    int phase = idx / (KPAD * NPAD);
    int rem = idx % (KPAD * NPAD);
    int k = rem / NPAD, n = rem % NPAD;
    float v = 0.f;
    if (k < K1 && n < NCOLS) v = (phase ? Wn : Ws)[(size_t)k * NCOLS + n];
    uint32_t h = __float_as_uint(v) & 0xFFFF0000u;
    hi[idx] = __ushort_as_bfloat16((unsigned short)(h >> 16));
    lo[idx] = __float2bfloat16(v - __uint_as_float(h));
}

// ======================== cp.async pipelined bf16x3 GEMM =====================
template <int KPAD, int NCOLS, int NPAD, bool RELU, bool WSPLIT>
__global__ void __launch_bounds__(256, 1)
gemm_mma(const __nv_bfloat16* __restrict__ As_hi, const __nv_bfloat16* __restrict__ As_lo,
         const __nv_bfloat16* __restrict__ An_hi, const __nv_bfloat16* __restrict__ An_lo,
         const __nv_bfloat16* __restrict__ W_hi, const __nv_bfloat16* __restrict__ W_lo,
         const float* __restrict__ bias, float* __restrict__ out,
         uint32_t* __restrict__ sp_hi, uint32_t* __restrict__ sp_lo, int split_rows) {
    constexpr int BK = 64;
    constexpr int AST = 72;
    constexpr int BST = 136;
    constexpr int ABYTES = 128 * AST * 2;
    constexpr int BBYTES = BK * BST * 2;
    constexpr int SSTRIDE = 2 * ABYTES + 2 * BBYTES;
    constexpr int CPP = KPAD / BK;
    constexpr int NCH = 2 * CPP;

    extern __shared__ char smem[];
    const uint32_t su = smem_u32(smem);

    const int tid = threadIdx.x;
    const int lane = tid & 31, wid = tid >> 5;
    const int wm = wid & 1, wn = wid >> 1;
    const int nBlock = blockIdx.x * 128, mBlock = blockIdx.y * 128;

    const int ar = tid >> 1;
    const int ab = (tid & 1) * 64;
    const int br = tid >> 4;
    const int bc = tid & 15;

    auto issue_chunk = [&](int c) {
        const int stage = c & 1;
        const int phase = c / CPP;
        const int k0 = (c % CPP) * BK;
        const __nv_bfloat16* Ahi = phase ? An_hi : As_hi;
        const __nv_bfloat16* Alo = phase ? An_lo : As_lo;
        const uint32_t sb = su + stage * SSTRIDE;
        {
            size_t g = (size_t)(mBlock + ar) * KPAD + k0 + ab / 2;
            uint32_t sa = sb + 2u * (uint32_t)(ar * AST) + (uint32_t)ab;
#pragma unroll
            for (int q = 0; q < 4; ++q) {
                cp_async16(sa + 16 * q, Ahi + g + 8 * q);
                cp_async16(sa + (uint32_t)ABYTES + 16 * q, Alo + g + 8 * q);
            }
        }
        {
            const __nv_bfloat16* wb =
                W_hi + (size_t)phase * KPAD * NPAD + (size_t)k0 * NPAD + nBlock;
            const __nv_bfloat16* wl =
                W_lo + (size_t)phase * KPAD * NPAD + (size_t)k0 * NPAD + nBlock;
#pragma unroll
            for (int it = 0; it < 4; ++it) {
                int r = br + it * 16;
                size_t g = (size_t)r * NPAD + bc * 8;
                uint32_t sbb = sb + 2u * (uint32_t)ABYTES +
                               2u * (uint32_t)(r * BST + bc * 8);
                cp_async16(sbb, wb + g);
                cp_async16(sbb + (uint32_t)BBYTES, wl + g);
            }
        }
        CP_COMMIT();
    };

    float acc[4][4][4];
#pragma unroll
    for (int i = 0; i < 4; i++)
#pragma unroll
        for (int j = 0; j < 4; j++)
#pragma unroll
            for (int r = 0; r < 4; r++) acc[i][j][r] = 0.f;

    const int lr = lane & 15;
    const int lc = (lane >> 4) * 8;
    const uint32_t aOff = 2u * (uint32_t)((wm * 64 + lr) * AST + lc);
    const uint32_t bOff = 2u * (uint32_t)ABYTES + 2u * (uint32_t)(lr * BST + wn * 32 + lc);

    issue_chunk(0);
    for (int c = 0; c < NCH; ++c) {
        if (c + 1 < NCH) {
            issue_chunk(c + 1);
            asm volatile("cp.async.wait_group 1;" ::: "memory");
        } else {
            asm volatile("cp.async.wait_group 0;" ::: "memory");
        }
        __syncthreads();
        const uint32_t sb = su + (c & 1) * SSTRIDE;
        const uint32_t aHiBase = sb + aOff;
        const uint32_t bHiBase = sb + bOff;
#pragma unroll
        for (int k16 = 0; k16 < BK / 16; ++k16) {
            const uint32_t kk = k16 * 16;
            uint32_t ah[4][4], bh[2][4];
#pragma unroll
            for (int p = 0; p < 2; ++p)
                ldsm4t(bh[p], bHiBase + 2u * (kk * BST + p * 16));
#pragma unroll
            for (int mt = 0; mt < 4; ++mt)
                ldsm4(ah[mt], aHiBase + 2u * (mt * 16 * AST + kk));
#pragma unroll
            for (int mt = 0; mt < 4; ++mt)
#pragma unroll
                for (int nt = 0; nt < 4; ++nt)
                    mma_bf16(acc[mt][nt], ah[mt], bh[nt >> 1][(nt & 1) * 2],
                             bh[nt >> 1][(nt & 1) * 2 + 1]);
            {
                uint32_t bl[2][4];
#pragma unroll
                for (int p = 0; p < 2; ++p)
                    ldsm4t(bl[p], bHiBase + (uint32_t)BBYTES + 2u * (kk * BST + p * 16));
#pragma unroll
                for (int mt = 0; mt < 4; ++mt)
#pragma unroll
                    for (int nt = 0; nt < 4; ++nt)
                        mma_bf16(acc[mt][nt], ah[mt], bl[nt >> 1][(nt & 1) * 2],
                                 bl[nt >> 1][(nt & 1) * 2 + 1]);
            }
            {
                uint32_t al[4][4];
#pragma unroll
                for (int mt = 0; mt < 4; ++mt)
                    ldsm4(al[mt], aHiBase + (uint32_t)ABYTES + 2u * (mt * 16 * AST + kk));
#pragma unroll
                for (int mt = 0; mt < 4; ++mt)
#pragma unroll
                    for (int nt = 0; nt < 4; ++nt)
                        mma_bf16(acc[mt][nt], al[mt], bh[nt >> 1][(nt & 1) * 2],
                                 bh[nt >> 1][(nt & 1) * 2 + 1]);
            }
        }
        __syncthreads();
    }

#pragma unroll
    for (int mt = 0; mt < 4; ++mt) {
        const int gmA = mBlock + wm * 64 + mt * 16 + (lane >> 2);
#pragma unroll
        for (int half = 0; half < 2; ++half) {
            const int gm = gmA + half * 8;
            float* orow = out + (size_t)gm * NCOLS;
#pragma unroll
            for (int nt = 0; nt < 4; ++nt) {
                const int gn = nBlock + wn * 32 + nt * 8 + (lane & 3) * 2;
                float v0 = acc[mt][nt][half * 2 + 0];
                float v1 = acc[mt][nt][half * 2 + 1];
                if constexpr (NCOLS % 128 == 0) {
                    v0 += __ldg(bias + gn);
                    v1 += __ldg(bias + gn + 1);
                    if (RELU) { v0 = fmaxf(v0, 0.f); v1 = fmaxf(v1, 0.f); }
                    *reinterpret_cast<float2*>(orow + gn) = make_float2(v0, v1);
                    if (WSPLIT && gm < split_rows) {
                        uint32_t h0 = __float_as_uint(v0) & 0xFFFF0000u;
                        uint32_t h1 = __float_as_uint(v1) & 0xFFFF0000u;
                        size_t so = (size_t)gm * (NCOLS / 2) + (gn >> 1);
                        sp_hi[so] = (h0 >> 16) | h1;
                        sp_lo[so] = cvt_bf16x2(v0 - __uint_as_float(h0),
                                               v1 - __uint_as_float(h1));
                    }
                } else {
                    if (gn < NCOLS) {
                        float v = v0 + __ldg(bias + gn);
                        if (RELU) v = fmaxf(v, 0.f);
                        orow[gn] = v;
                    }
                    if (gn + 1 < NCOLS) {
                        float v = v1 + __ldg(bias + gn + 1);
                        if (RELU) v = fmaxf(v, 0.f);
                        orow[gn + 1] = v;
                    }
                }
            }
        }
    }
}

// ======================== host launcher =====================================
static inline int cdiv_host(long long a, long long b) { return (int)((a + b - 1) / b); }

extern "C" void kernel_launch(void* const* d_in, const int* in_sizes, int n_in,
                              void* d_out, int out_size) {
    (void)in_sizes; (void)n_in; (void)out_size;
    const float* x   = (const float*)d_in[0];
    const int* es0   = (const int*)d_in[1];
    const int* ed0   = (const int*)d_in[2];
    const int* es1   = (const int*)d_in[3];
    const int* ed1   = (const int*)d_in[4];
    const int* es2   = (const int*)d_in[5];
    const int* ed2   = (const int*)d_in[6];
    const float* Ws0 = (const float*)d_in[7];
    const float* Wn0 = (const float*)d_in[8];
    const float* b0  = (const float*)d_in[9];
    const float* Ws1 = (const float*)d_in[10];
    const float* Wn1 = (const float*)d_in[11];
    const float* b1  = (const float*)d_in[12];
    const float* Ws2 = (const float*)d_in[13];
    const float* Wn2 = (const float*)d_in[14];
    const float* b2  = (const float*)d_in[15];
    float* out = (float*)d_out;

    float *h1, *h2;
    cudaGetSymbolAddress((void**)&h1, g_h1);
    cudaGetSymbolAddress((void**)&h2, g_h2);
    int *cnt, *cur, *off, *cursor, *csc;
    cudaGetSymbolAddress((void**)&cnt, g_cnt);
    cudaGetSymbolAddress((void**)&cur, g_cur);
    cudaGetSymbolAddress((void**)&off, g_off);
    cudaGetSymbolAddress((void**)&cursor, g_cursor);
    cudaGetSymbolAddress((void**)&csc, g_csc);

    __nv_bfloat16 *xs_hi, *xs_lo, *a0_hi, *a0_lo, *h1s_hi, *h1s_lo;
    __nv_bfloat16 *a1_hi, *a1_lo, *h2s_hi, *h2s_lo, *a2_hi, *a2_lo;
    cudaGetSymbolAddress((void**)&xs_hi, g_xs_hi);
    cudaGetSymbolAddress((void**)&xs_lo, g_xs_lo);
    cudaGetSymbolAddress((void**)&a0_hi, g_a0_hi);
    cudaGetSymbolAddress((void**)&a0_lo, g_a0_lo);
    cudaGetSymbolAddress((void**)&h1s_hi, g_h1s_hi);
    cudaGetSymbolAddress((void**)&h1s_lo, g_h1s_lo);
    cudaGetSymbolAddress((void**)&a1_hi, g_a1_hi);
    cudaGetSymbolAddress((void**)&a1_lo, g_a1_lo);
    cudaGetSymbolAddress((void**)&h2s_hi, g_h2s_hi);
    cudaGetSymbolAddress((void**)&h2s_lo, g_h2s_lo);
    cudaGetSymbolAddress((void**)&a2_hi, g_a2_hi);
    cudaGetSymbolAddress((void**)&a2_lo, g_a2_lo);
    __nv_bfloat16 *w0h, *w0l, *w1h, *w1l, *w2h, *w2l;
    cudaGetSymbolAddress((void**)&w0h, g_w0_hi);
    cudaGetSymbolAddress((void**)&w0l, g_w0_lo);
    cudaGetSymbolAddress((void**)&w1h, g_w1_hi);
    cudaGetSymbolAddress((void**)&w1l, g_w1_lo);
    cudaGetSymbolAddress((void**)&w2h, g_w2_hi);
    cudaGetSymbolAddress((void**)&w2l, g_w2_lo);

    const int T = 256;
    constexpr int SMEM_SZ = 2 * (2 * 128 * 72 * 2 + 2 * 64 * 136 * 2);  // 143360

    cudaFuncSetAttribute(gemm_mma<128, 256, 256, true, true>,
                         cudaFuncAttributeMaxDynamicSharedMemorySize, SMEM_SZ);
    cudaFuncSetAttribute(gemm_mma<256, 256, 256, true, true>,
                         cudaFuncAttributeMaxDynamicSharedMemorySize, SMEM_SZ);
    cudaFuncSetAttribute(gemm_mma<256, 47, 128, false, false>,
                         cudaFuncAttributeMaxDynamicSharedMemorySize, SMEM_SZ);

    // CSC build + gather-mean-split for one layer.
    auto aggregate = [&](const int* esrc, const int* edst, int nE, int ndst) {
        zero_int<<<cdiv_host(ndst, T), T>>>(cnt, ndst);
        zero_int<<<cdiv_host(ndst, T), T>>>(cur, ndst);
        zero_int<<<1, 32>>>(cursor, 1);
        count_kern<<<cdiv_host(nE, T), T>>>(edst, nE, cnt);
        reserve_kern<<<cdiv_host(ndst, 256), 256>>>(cnt, off, ndst, cursor);
        fill_kern<<<cdiv_host(nE, T), T>>>(esrc, edst, nE, off, cur, csc);
    };

    // ---- weight prep + x split
    prep_w<100, 256, 128, 256><<<cdiv_host(2 * 128 * 256, T), T>>>(Ws0, Wn0, w0h, w0l);
    prep_w<256, 256, 256, 256><<<cdiv_host(2 * 256 * 256, T), T>>>(Ws1, Wn1, w1h, w1l);
    prep_w<256, 47, 256, 128><<<cdiv_host(2 * 256 * 128, T), T>>>(Ws2, Wn2, w2h, w2l);
    split_kern<100, 128><<<cdiv_host((long long)kN1 * 32, T), T>>>(
        x, kN1, (uint2*)xs_hi, (uint2*)xs_lo);

    // ---------------- layer 0: x[1M,100] -> h1[262144,256]
    aggregate(es0, ed0, kE0, kN1);
    gather_split<100, 128><<<kN1 / 8, T>>>(x, off, cnt, csc, kN1,
                                           (uint2*)a0_hi, (uint2*)a0_lo);
    gemm_mma<128, 256, 256, true, true><<<dim3(2, kN1 / 128), T, SMEM_SZ>>>(
        xs_hi, xs_lo, a0_hi, a0_lo, w0h, w0l, b0, h1,
        (uint32_t*)h1s_hi, (uint32_t*)h1s_lo, kN2);

    // ---------------- layer 1: h1 -> h2[32768,256]
    aggregate(es1, ed1, kE1, kN2);
    gather_split<256, 256><<<kN2 / 8, T>>>(h1, off, cnt, csc, kN2,
                                           (uint2*)a1_hi, (uint2*)a1_lo);
    gemm_mma<256, 256, 256, true, true><<<dim3(2, kN2 / 128), T, SMEM_SZ>>>(
        h1s_hi, h1s_lo, a1_hi, a1_lo, w1h, w1l, b1, h2,
        (uint32_t*)h2s_hi, (uint32_t*)h2s_lo, kN3);

    // ---------------- layer 2: h2 -> out[8192,47]
    aggregate(es2, ed2, kE2, kN3);
    gather_split<256, 256><<<kN3 / 8, T>>>(h2, off, cnt, csc, kN3,
                                           (uint2*)a2_hi, (uint2*)a2_lo);
    gemm_mma<256, 47, 128, false, false><<<dim3(1, kN3 / 128), T, SMEM_SZ>>>(
        h2s_hi, h2s_lo, a2_hi, a2_lo, w2h, w2l, b2, out,
        nullptr, nullptr, 0);
}

// round 7
// speedup vs baseline: 2.3346x; 1.0449x over previous
#include <cuda_runtime.h>
#include <cuda_bf16.h>
#include <cstdint>
#include <cstddef>

// ---------------------------------------------------------------------------
// SAGE 3-layer GraphSAGE.
//   One fused CSC build for all 3 layers (zero/count/reserve/fill) ->
//   per-layer warp-per-dst gather-mean (4x edge-unrolled) emitting bf16 hi/lo
//   splits -> cp.async-pipelined mma.sync bf16x3 dual GEMM (bias+relu epilogue
//   emitting next layer's self split).
// Side stream (event fork/join, graph-capturable) runs split_x + weight prep
// concurrently with CSC build + gather0.
// ---------------------------------------------------------------------------

namespace {
constexpr int kN1 = 262144, kN2 = 32768, kN3 = 8192;
constexpr int kE0 = 1310720, kE1 = 327680, kE2 = 81920;
constexpr int kF = 100, kH = 256, kC = 47;
constexpr int kNT = kN1 + kN2 + kN3;          // 303104 (multiple of 256)
constexpr int kET = kE0 + kE1 + kE2;          // 1720320
}  // namespace

// -------- fp32 activations (gather sources) ---------------------------------
__device__ float g_h1[(size_t)kN1 * kH];
__device__ float g_h2[(size_t)kN2 * kH];

// -------- CSC scratch: one int pool ------------------------------------------
// [0,kNT): cnt  [kNT,2kNT): cur  [2kNT, 2kNT+3): cursors
__device__ int g_ints[2 * kNT + 3];
__device__ int g_off[kNT];
__device__ int g_csc[kET];

// -------- bf16 split operand buffers (K padded to 128/256) ------------------
__device__ __nv_bfloat16 g_xs_hi[(size_t)kN1 * 128], g_xs_lo[(size_t)kN1 * 128];
__device__ __nv_bfloat16 g_a0_hi[(size_t)kN1 * 128], g_a0_lo[(size_t)kN1 * 128];
__device__ __nv_bfloat16 g_h1s_hi[(size_t)kN2 * 256], g_h1s_lo[(size_t)kN2 * 256];
__device__ __nv_bfloat16 g_a1_hi[(size_t)kN2 * 256], g_a1_lo[(size_t)kN2 * 256];
__device__ __nv_bfloat16 g_h2s_hi[(size_t)kN3 * 256], g_h2s_lo[(size_t)kN3 * 256];
__device__ __nv_bfloat16 g_a2_hi[(size_t)kN3 * 256], g_a2_lo[(size_t)kN3 * 256];

// -------- pre-split weights: [2 phases][KPAD][NPAD] -------------------------
__device__ __nv_bfloat16 g_w0_hi[2 * 128 * 256], g_w0_lo[2 * 128 * 256];
__device__ __nv_bfloat16 g_w1_hi[2 * 256 * 256], g_w1_lo[2 * 256 * 256];
__device__ __nv_bfloat16 g_w2_hi[2 * 256 * 128], g_w2_lo[2 * 256 * 128];

// ======================== PTX helpers (arch-agnostic) ========================
__device__ __forceinline__ uint32_t smem_u32(const void* p) {
    return (uint32_t)__cvta_generic_to_shared(p);
}
__device__ __forceinline__ void ldsm4(uint32_t* r, uint32_t addr) {
    asm volatile("ldmatrix.sync.aligned.m8n8.x4.shared.b16 {%0,%1,%2,%3}, [%4];"
                 : "=r"(r[0]), "=r"(r[1]), "=r"(r[2]), "=r"(r[3]) : "r"(addr));
}
__device__ __forceinline__ void ldsm4t(uint32_t* r, uint32_t addr) {
    asm volatile("ldmatrix.sync.aligned.m8n8.x4.trans.shared.b16 {%0,%1,%2,%3}, [%4];"
                 : "=r"(r[0]), "=r"(r[1]), "=r"(r[2]), "=r"(r[3]) : "r"(addr));
}
__device__ __forceinline__ void mma_bf16(float* d, const uint32_t* a,
                                         uint32_t b0, uint32_t b1) {
    asm volatile(
        "mma.sync.aligned.m16n8k16.row.col.f32.bf16.bf16.f32 "
        "{%0,%1,%2,%3}, {%4,%5,%6,%7}, {%8,%9}, {%0,%1,%2,%3};"
        : "+f"(d[0]), "+f"(d[1]), "+f"(d[2]), "+f"(d[3])
        : "r"(a[0]), "r"(a[1]), "r"(a[2]), "r"(a[3]), "r"(b0), "r"(b1));
}
__device__ __forceinline__ uint32_t cvt_bf16x2(float a, float b) {
    uint32_t r;
    asm("cvt.rn.bf16x2.f32 %0, %1, %2;" : "=r"(r) : "f"(b), "f"(a));
    return r;
}
__device__ __forceinline__ void cp_async16(uint32_t saddr, const void* gptr) {
    asm volatile("cp.async.ca.shared.global [%0], [%1], 16;"
                 :: "r"(saddr), "l"(gptr));
}
#define CP_COMMIT() asm volatile("cp.async.commit_group;" ::: "memory")

// ======================== fused CSC build ====================================
__global__ void zero_int(int* __restrict__ p, int n) {
    int i = blockIdx.x * blockDim.x + threadIdx.x;
    if (i < n) p[i] = 0;
}
__global__ void count3(const int* __restrict__ ed0, const int* __restrict__ ed1,
                       const int* __restrict__ ed2, int* __restrict__ cnt) {
    int i = blockIdx.x * blockDim.x + threadIdx.x;
    if (i < kE0) {
        atomicAdd(cnt + __ldg(ed0 + i), 1);
    } else if (i < kE0 + kE1) {
        atomicAdd(cnt + kN1 + __ldg(ed1 + (i - kE0)), 1);
    } else if (i < kET) {
        atomicAdd(cnt + kN1 + kN2 + __ldg(ed2 + (i - kE0 - kE1)), 1);
    }
}
// Segmented block-scan reservation (segments are multiples of 256).
__global__ void reserve3(const int* __restrict__ cnt, int* __restrict__ off,
                         int* __restrict__ cursor) {
    __shared__ int s[256];
    __shared__ int base;
    int b = blockIdx.x, tid = threadIdx.x;
    int seg, segBase;
    if (b < kN1 / 256)               { seg = 0; segBase = 0; }
    else if (b < (kN1 + kN2) / 256)  { seg = 1; segBase = kN1; }
    else                             { seg = 2; segBase = kN1 + kN2; }
    int i = b * 256 + tid;           // global concatenated index
    int v = __ldg(cnt + i);
    s[tid] = v;
    __syncthreads();
#pragma unroll
    for (int dd = 1; dd < 256; dd <<= 1) {
        int t = (tid >= dd) ? s[tid - dd] : 0;
        __syncthreads();
        s[tid] += t;
        __syncthreads();
    }
    if (tid == 255) base = atomicAdd(cursor + seg, s[255]);
    __syncthreads();
    off[i] = base + s[tid] - v;
    (void)segBase;
}
__global__ void fill3(const int* __restrict__ es0, const int* __restrict__ ed0,
                      const int* __restrict__ es1, const int* __restrict__ ed1,
                      const int* __restrict__ es2, const int* __restrict__ ed2,
                      const int* __restrict__ off, int* __restrict__ cur,
                      int* __restrict__ csc) {
    int i = blockIdx.x * blockDim.x + threadIdx.x;
    if (i < kE0) {
        int d = __ldg(ed0 + i);
        int p = atomicAdd(cur + d, 1);
        csc[__ldg(off + d) + p] = __ldg(es0 + i);
    } else if (i < kE0 + kE1) {
        int j = i - kE0;
        int d = kN1 + __ldg(ed1 + j);
        int p = atomicAdd(cur + d, 1);
        csc[kE0 + __ldg(off + d) + p] = __ldg(es1 + j);
    } else if (i < kET) {
        int j = i - kE0 - kE1;
        int d = kN1 + kN2 + __ldg(ed2 + j);
        int p = atomicAdd(cur + d, 1);
        csc[kE0 + kE1 + __ldg(off + d) + p] = __ldg(es2 + j);
    }
}

// ======================== gather-mean + split (4x unrolled) ==================
template <int K, int KPAD>
__global__ void gather_split(const float* __restrict__ feat,
                             const int* __restrict__ off,
                             const int* __restrict__ cnt,
                             const int* __restrict__ csc, int ndst,
                             uint2* __restrict__ hi, uint2* __restrict__ lo) {
    constexpr int NV = K / 4;
    constexpr int PV = KPAD / 4;
    constexpr int PER = (PV + 31) / 32;
    int d = (blockIdx.x * blockDim.x + threadIdx.x) >> 5;
    int lane = threadIdx.x & 31;
    if (d >= ndst) return;
    int o0 = __ldg(off + d);
    int deg = __ldg(cnt + d);
    float4 acc[PER];
#pragma unroll
    for (int p = 0; p < PER; ++p) acc[p] = make_float4(0.f, 0.f, 0.f, 0.f);
    int e = 0;
    for (; e + 4 <= deg; e += 4) {
        int s0 = __ldg(csc + o0 + e + 0);
        int s1 = __ldg(csc + o0 + e + 1);
        int s2 = __ldg(csc + o0 + e + 2);
        int s3 = __ldg(csc + o0 + e + 3);
        const float4* r0 = reinterpret_cast<const float4*>(feat + (size_t)s0 * K);
        const float4* r1 = reinterpret_cast<const float4*>(feat + (size_t)s1 * K);
        const float4* r2 = reinterpret_cast<const float4*>(feat + (size_t)s2 * K);
        const float4* r3 = reinterpret_cast<const float4*>(feat + (size_t)s3 * K);
#pragma unroll
        for (int p = 0; p < PER; ++p) {
            int v = lane + 32 * p;
            if (v < NV) {
                float4 f0 = __ldg(r0 + v);
                float4 f1 = __ldg(r1 + v);
                float4 f2 = __ldg(r2 + v);
                float4 f3 = __ldg(r3 + v);
                acc[p].x += (f0.x + f1.x) + (f2.x + f3.x);
                acc[p].y += (f0.y + f1.y) + (f2.y + f3.y);
                acc[p].z += (f0.z + f1.z) + (f2.z + f3.z);
                acc[p].w += (f0.w + f1.w) + (f2.w + f3.w);
            }
        }
    }
    for (; e < deg; ++e) {
        int s = __ldg(csc + o0 + e);
        const float4* row = reinterpret_cast<const float4*>(feat + (size_t)s * K);
#pragma unroll
        for (int p = 0; p < PER; ++p) {
            int v = lane + 32 * p;
            if (v < NV) {
                float4 f = __ldg(row + v);
                acc[p].x += f.x; acc[p].y += f.y; acc[p].z += f.z; acc[p].w += f.w;
            }
        }
    }
    float r = 1.f / fmaxf((float)deg, 1.f);
#pragma unroll
    for (int p = 0; p < PER; ++p) {
        int v = lane + 32 * p;
        if (v >= PV) continue;
        float4 w = make_float4(0.f, 0.f, 0.f, 0.f);
        if (v < NV) {
            w.x = acc[p].x * r; w.y = acc[p].y * r;
            w.z = acc[p].z * r; w.w = acc[p].w * r;
        }
        uint32_t hx = __float_as_uint(w.x) & 0xFFFF0000u;
        uint32_t hy = __float_as_uint(w.y) & 0xFFFF0000u;
        uint32_t hz = __float_as_uint(w.z) & 0xFFFF0000u;
        uint32_t hw = __float_as_uint(w.w) & 0xFFFF0000u;
        uint2 ho, lv;
        ho.x = (hx >> 16) | hy;
        ho.y = (hz >> 16) | hw;
        lv.x = cvt_bf16x2(w.x - __uint_as_float(hx), w.y - __uint_as_float(hy));
        lv.y = cvt_bf16x2(w.z - __uint_as_float(hz), w.w - __uint_as_float(hw));
        size_t oidx = (size_t)d * PV + v;
        hi[oidx] = ho;
        lo[oidx] = lv;
    }
}

// ======================== misc small kernels =================================
template <int K, int KPAD>
__global__ void split_kern(const float* __restrict__ in, int rows,
                           uint2* __restrict__ hi, uint2* __restrict__ lo) {
    constexpr int PR = KPAD / 4;
    int idx = blockIdx.x * blockDim.x + threadIdx.x;
    if (idx >= rows * PR) return;
    int row = idx / PR, kq = idx % PR;
    int k4 = kq * 4;
    float4 v = make_float4(0.f, 0.f, 0.f, 0.f);
    if (k4 < K)
        v = *reinterpret_cast<const float4*>(in + (size_t)row * K + k4);
    uint32_t hx = __float_as_uint(v.x) & 0xFFFF0000u;
    uint32_t hy = __float_as_uint(v.y) & 0xFFFF0000u;
    uint32_t hz = __float_as_uint(v.z) & 0xFFFF0000u;
    uint32_t hw = __float_as_uint(v.w) & 0xFFFF0000u;
    uint2 ho, lv;
    ho.x = (hx >> 16) | hy;
    ho.y = (hz >> 16) | hw;
    lv.x = cvt_bf16x2(v.x - __uint_as_float(hx), v.y - __uint_as_float(hy));
    lv.y = cvt_bf16x2(v.z - __uint_as_float(hz), v.w - __uint_as_float(hw));
    size_t o = (size_t)row * PR + kq;
    hi[o] = ho;
    lo[o] = lv;
}

template <int K1, int NCOLS, int KPAD, int NPAD>
__global__ void prep_w(const float* __restrict__ Ws, const float* __restrict__ Wn,
                       __nv_bfloat16* __restrict__ hi, __nv_bfloat16* __restrict__ lo) {
    int idx = blockIdx.x * blockDim.x + threadIdx.x;
    constexpr int TOT = 2 * KPAD * NPAD;
    if (idx >= TOT) return;
    int phase = idx / (KPAD * NPAD);
    int rem = idx % (KPAD * NPAD);
    int k = rem / NPAD, n = rem % NPAD;
    float v = 0.f;
    if (k < K1 && n < NCOLS) v = (phase ? Wn : Ws)[(size_t)k * NCOLS + n];
    uint32_t h = __float_as_uint(v) & 0xFFFF0000u;
    hi[idx] = __ushort_as_bfloat16((unsigned short)(h >> 16));
    lo[idx] = __float2bfloat16(v - __uint_as_float(h));
}

// ======================== cp.async pipelined bf16x3 GEMM =====================
template <int KPAD, int NCOLS, int NPAD, bool RELU, bool WSPLIT>
__global__ void __launch_bounds__(256, 1)
gemm_mma(const __nv_bfloat16* __restrict__ As_hi, const __nv_bfloat16* __restrict__ As_lo,
         const __nv_bfloat16* __restrict__ An_hi, const __nv_bfloat16* __restrict__ An_lo,
         const __nv_bfloat16* __restrict__ W_hi, const __nv_bfloat16* __restrict__ W_lo,
         const float* __restrict__ bias, float* __restrict__ out,
         uint32_t* __restrict__ sp_hi, uint32_t* __restrict__ sp_lo, int split_rows) {
    constexpr int BK = 64;
    constexpr int AST = 72;
    constexpr int BST = 136;
    constexpr int ABYTES = 128 * AST * 2;
    constexpr int BBYTES = BK * BST * 2;
    constexpr int SSTRIDE = 2 * ABYTES + 2 * BBYTES;
    constexpr int CPP = KPAD / BK;
    constexpr int NCH = 2 * CPP;

    extern __shared__ char smem[];
    const uint32_t su = smem_u32(smem);

    const int tid = threadIdx.x;
    const int lane = tid & 31, wid = tid >> 5;
    const int wm = wid & 1, wn = wid >> 1;
    const int nBlock = blockIdx.x * 128, mBlock = blockIdx.y * 128;

    const int ar = tid >> 1;
    const int ab = (tid & 1) * 64;
    const int br = tid >> 4;
    const int bc = tid & 15;

    auto issue_chunk = [&](int c) {
        const int stage = c & 1;
        const int phase = c / CPP;
        const int k0 = (c % CPP) * BK;
        const __nv_bfloat16* Ahi = phase ? An_hi : As_hi;
        const __nv_bfloat16* Alo = phase ? An_lo : As_lo;
        const uint32_t sb = su + stage * SSTRIDE;
        {
            size_t g = (size_t)(mBlock + ar) * KPAD + k0 + ab / 2;
            uint32_t sa = sb + 2u * (uint32_t)(ar * AST) + (uint32_t)ab;
#pragma unroll
            for (int q = 0; q < 4; ++q) {
                cp_async16(sa + 16 * q, Ahi + g + 8 * q);
                cp_async16(sa + (uint32_t)ABYTES + 16 * q, Alo + g + 8 * q);
            }
        }
        {
            const __nv_bfloat16* wb =
                W_hi + (size_t)phase * KPAD * NPAD + (size_t)k0 * NPAD + nBlock;
            const __nv_bfloat16* wl =
                W_lo + (size_t)phase * KPAD * NPAD + (size_t)k0 * NPAD + nBlock;
#pragma unroll
            for (int it = 0; it < 4; ++it) {
                int r = br + it * 16;
                size_t g = (size_t)r * NPAD + bc * 8;
                uint32_t sbb = sb + 2u * (uint32_t)ABYTES +
                               2u * (uint32_t)(r * BST + bc * 8);
                cp_async16(sbb, wb + g);
                cp_async16(sbb + (uint32_t)BBYTES, wl + g);
            }
        }
        CP_COMMIT();
    };

    float acc[4][4][4];
#pragma unroll
    for (int i = 0; i < 4; i++)
#pragma unroll
        for (int j = 0; j < 4; j++)
#pragma unroll
            for (int r = 0; r < 4; r++) acc[i][j][r] = 0.f;

    const int lr = lane & 15;
    const int lc = (lane >> 4) * 8;
    const uint32_t aOff = 2u * (uint32_t)((wm * 64 + lr) * AST + lc);
    const uint32_t bOff = 2u * (uint32_t)ABYTES + 2u * (uint32_t)(lr * BST + wn * 32 + lc);

    issue_chunk(0);
    for (int c = 0; c < NCH; ++c) {
        if (c + 1 < NCH) {
            issue_chunk(c + 1);
            asm volatile("cp.async.wait_group 1;" ::: "memory");
        } else {
            asm volatile("cp.async.wait_group 0;" ::: "memory");
        }
        __syncthreads();
        const uint32_t sb = su + (c & 1) * SSTRIDE;
        const uint32_t aHiBase = sb + aOff;
        const uint32_t bHiBase = sb + bOff;
#pragma unroll
        for (int k16 = 0; k16 < BK / 16; ++k16) {
            const uint32_t kk = k16 * 16;
            uint32_t ah[4][4], bh[2][4];
#pragma unroll
            for (int p = 0; p < 2; ++p)
                ldsm4t(bh[p], bHiBase + 2u * (kk * BST + p * 16));
#pragma unroll
            for (int mt = 0; mt < 4; ++mt)
                ldsm4(ah[mt], aHiBase + 2u * (mt * 16 * AST + kk));
#pragma unroll
            for (int mt = 0; mt < 4; ++mt)
#pragma unroll
                for (int nt = 0; nt < 4; ++nt)
                    mma_bf16(acc[mt][nt], ah[mt], bh[nt >> 1][(nt & 1) * 2],
                             bh[nt >> 1][(nt & 1) * 2 + 1]);
            {
                uint32_t bl[2][4];
#pragma unroll
                for (int p = 0; p < 2; ++p)
                    ldsm4t(bl[p], bHiBase + (uint32_t)BBYTES + 2u * (kk * BST + p * 16));
#pragma unroll
                for (int mt = 0; mt < 4; ++mt)
#pragma unroll
                    for (int nt = 0; nt < 4; ++nt)
                        mma_bf16(acc[mt][nt], ah[mt], bl[nt >> 1][(nt & 1) * 2],
                                 bl[nt >> 1][(nt & 1) * 2 + 1]);
            }
            {
                uint32_t al[4][4];
#pragma unroll
                for (int mt = 0; mt < 4; ++mt)
                    ldsm4(al[mt], aHiBase + (uint32_t)ABYTES + 2u * (mt * 16 * AST + kk));
#pragma unroll
                for (int mt = 0; mt < 4; ++mt)
#pragma unroll
                    for (int nt = 0; nt < 4; ++nt)
                        mma_bf16(acc[mt][nt], al[mt], bh[nt >> 1][(nt & 1) * 2],
                                 bh[nt >> 1][(nt & 1) * 2 + 1]);
            }
        }
        __syncthreads();
    }

#pragma unroll
    for (int mt = 0; mt < 4; ++mt) {
        const int gmA = mBlock + wm * 64 + mt * 16 + (lane >> 2);
#pragma unroll
        for (int half = 0; half < 2; ++half) {
            const int gm = gmA + half * 8;
            float* orow = out + (size_t)gm * NCOLS;
#pragma unroll
            for (int nt = 0; nt < 4; ++nt) {
                const int gn = nBlock + wn * 32 + nt * 8 + (lane & 3) * 2;
                float v0 = acc[mt][nt][half * 2 + 0];
                float v1 = acc[mt][nt][half * 2 + 1];
                if constexpr (NCOLS % 128 == 0) {
                    v0 += __ldg(bias + gn);
                    v1 += __ldg(bias + gn + 1);
                    if (RELU) { v0 = fmaxf(v0, 0.f); v1 = fmaxf(v1, 0.f); }
                    *reinterpret_cast<float2*>(orow + gn) = make_float2(v0, v1);
                    if (WSPLIT && gm < split_rows) {
                        uint32_t h0 = __float_as_uint(v0) & 0xFFFF0000u;
                        uint32_t h1 = __float_as_uint(v1) & 0xFFFF0000u;
                        size_t so = (size_t)gm * (NCOLS / 2) + (gn >> 1);
                        sp_hi[so] = (h0 >> 16) | h1;
                        sp_lo[so] = cvt_bf16x2(v0 - __uint_as_float(h0),
                                               v1 - __uint_as_float(h1));
                    }
                } else {
                    if (gn < NCOLS) {
                        float v = v0 + __ldg(bias + gn);
                        if (RELU) v = fmaxf(v, 0.f);
                        orow[gn] = v;
                    }
                    if (gn + 1 < NCOLS) {
                        float v = v1 + __ldg(bias + gn + 1);
                        if (RELU) v = fmaxf(v, 0.f);
                        orow[gn + 1] = v;
                    }
                }
            }
        }
    }
}

// ======================== host launcher =====================================
static inline int cdiv_host(long long a, long long b) { return (int)((a + b - 1) / b); }

extern "C" void kernel_launch(void* const* d_in, const int* in_sizes, int n_in,
                              void* d_out, int out_size) {
    (void)in_sizes; (void)n_in; (void)out_size;
    const float* x   = (const float*)d_in[0];
    const int* es0   = (const int*)d_in[1];
    const int* ed0   = (const int*)d_in[2];
    const int* es1   = (const int*)d_in[3];
    const int* ed1   = (const int*)d_in[4];
    const int* es2   = (const int*)d_in[5];
    const int* ed2   = (const int*)d_in[6];
    const float* Ws0 = (const float*)d_in[7];
    const float* Wn0 = (const float*)d_in[8];
    const float* b0  = (const float*)d_in[9];
    const float* Ws1 = (const float*)d_in[10];
    const float* Wn1 = (const float*)d_in[11];
    const float* b1  = (const float*)d_in[12];
    const float* Ws2 = (const float*)d_in[13];
    const float* Wn2 = (const float*)d_in[14];
    const float* b2  = (const float*)d_in[15];
    float* out = (float*)d_out;

    float *h1, *h2;
    cudaGetSymbolAddress((void**)&h1, g_h1);
    cudaGetSymbolAddress((void**)&h2, g_h2);
    int *ints, *off, *csc;
    cudaGetSymbolAddress((void**)&ints, g_ints);
    cudaGetSymbolAddress((void**)&off, g_off);
    cudaGetSymbolAddress((void**)&csc, g_csc);
    int* cnt = ints;
    int* cur = ints + kNT;
    int* cursor = ints + 2 * kNT;

    __nv_bfloat16 *xs_hi, *xs_lo, *a0_hi, *a0_lo, *h1s_hi, *h1s_lo;
    __nv_bfloat16 *a1_hi, *a1_lo, *h2s_hi, *h2s_lo, *a2_hi, *a2_lo;
    cudaGetSymbolAddress((void**)&xs_hi, g_xs_hi);
    cudaGetSymbolAddress((void**)&xs_lo, g_xs_lo);
    cudaGetSymbolAddress((void**)&a0_hi, g_a0_hi);
    cudaGetSymbolAddress((void**)&a0_lo, g_a0_lo);
    cudaGetSymbolAddress((void**)&h1s_hi, g_h1s_hi);
    cudaGetSymbolAddress((void**)&h1s_lo, g_h1s_lo);
    cudaGetSymbolAddress((void**)&a1_hi, g_a1_hi);
    cudaGetSymbolAddress((void**)&a1_lo, g_a1_lo);
    cudaGetSymbolAddress((void**)&h2s_hi, g_h2s_hi);
    cudaGetSymbolAddress((void**)&h2s_lo, g_h2s_lo);
    cudaGetSymbolAddress((void**)&a2_hi, g_a2_hi);
    cudaGetSymbolAddress((void**)&a2_lo, g_a2_lo);
    __nv_bfloat16 *w0h, *w0l, *w1h, *w1l, *w2h, *w2l;
    cudaGetSymbolAddress((void**)&w0h, g_w0_hi);
    cudaGetSymbolAddress((void**)&w0l, g_w0_lo);
    cudaGetSymbolAddress((void**)&w1h, g_w1_hi);
    cudaGetSymbolAddress((void**)&w1l, g_w1_lo);
    cudaGetSymbolAddress((void**)&w2h, g_w2_hi);
    cudaGetSymbolAddress((void**)&w2l, g_w2_lo);

    const int T = 256;
    constexpr int SMEM_SZ = 2 * (2 * 128 * 72 * 2 + 2 * 64 * 136 * 2);  // 143360

    cudaFuncSetAttribute(gemm_mma<128, 256, 256, true, true>,
                         cudaFuncAttributeMaxDynamicSharedMemorySize, SMEM_SZ);
    cudaFuncSetAttribute(gemm_mma<256, 256, 256, true, true>,
                         cudaFuncAttributeMaxDynamicSharedMemorySize, SMEM_SZ);
    cudaFuncSetAttribute(gemm_mma<256, 47, 128, false, false>,
                         cudaFuncAttributeMaxDynamicSharedMemorySize, SMEM_SZ);

    // Side stream + events (created once; identical captured work every call).
    static cudaStream_t side = nullptr;
    static cudaEvent_t evFork = nullptr, evJoin = nullptr;
    if (!side) {
        cudaStreamCreateWithFlags(&side, cudaStreamNonBlocking);
        cudaEventCreateWithFlags(&evFork, cudaEventDisableTiming);
        cudaEventCreateWithFlags(&evJoin, cudaEventDisableTiming);
    }

    // ---- fork: side stream does split_x + weight prep (independent work)
    cudaEventRecord(evFork, 0);
    cudaStreamWaitEvent(side, evFork, 0);
    split_kern<100, 128><<<cdiv_host((long long)kN1 * 32, T), T, 0, side>>>(
        x, kN1, (uint2*)xs_hi, (uint2*)xs_lo);
    prep_w<100, 256, 128, 256><<<cdiv_host(2 * 128 * 256, T), T, 0, side>>>(
        Ws0, Wn0, w0h, w0l);
    prep_w<256, 256, 256, 256><<<cdiv_host(2 * 256 * 256, T), T, 0, side>>>(
        Ws1, Wn1, w1h, w1l);
    prep_w<256, 47, 256, 128><<<cdiv_host(2 * 256 * 128, T), T, 0, side>>>(
        Ws2, Wn2, w2h, w2l);
    cudaEventRecord(evJoin, side);

    // ---- main: fused CSC build for all 3 layers, then gather0
    zero_int<<<cdiv_host(2 * kNT + 3, T), T>>>(ints, 2 * kNT + 3);
    count3<<<cdiv_host(kET, T), T>>>(ed0, ed1, ed2, cnt);
    reserve3<<<kNT / 256, 256>>>(cnt, off, cursor);
    fill3<<<cdiv_host(kET, T), T>>>(es0, ed0, es1, ed1, es2, ed2, off, cur, csc);

    gather_split<100, 128><<<kN1 / 8, T>>>(x, off, cnt, csc, kN1,
                                           (uint2*)a0_hi, (uint2*)a0_lo);

    // ---- join before gemm0 (needs xs + weights)
    cudaStreamWaitEvent(0, evJoin, 0);

    gemm_mma<128, 256, 256, true, true><<<dim3(2, kN1 / 128), T, SMEM_SZ>>>(
        xs_hi, xs_lo, a0_hi, a0_lo, w0h, w0l, b0, h1,
        (uint32_t*)h1s_hi, (uint32_t*)h1s_lo, kN2);

    // ---------------- layer 1
    gather_split<256, 256><<<kN2 / 8, T>>>(h1, off + kN1, cnt + kN1, csc + kE0,
                                           kN2, (uint2*)a1_hi, (uint2*)a1_lo);
    gemm_mma<256, 256, 256, true, true><<<dim3(2, kN2 / 128), T, SMEM_SZ>>>(
        h1s_hi, h1s_lo, a1_hi, a1_lo, w1h, w1l, b1, h2,
        (uint32_t*)h2s_hi, (uint32_t*)h2s_lo, kN3);

    // ---------------- layer 2
    gather_split<256, 256><<<kN3 / 8, T>>>(h2, off + kN1 + kN2, cnt + kN1 + kN2,
                                           csc + kE0 + kE1, kN3,
                                           (uint2*)a2_hi, (uint2*)a2_lo);
    gemm_mma<256, 47, 128, false, false><<<dim3(1, kN3 / 128), T, SMEM_SZ>>>(
        h2s_hi, h2s_lo, a2_hi, a2_lo, w2h, w2l, b2, out,
        nullptr, nullptr, 0);
}